// round 8
// baseline (speedup 1.0000x reference)
#include <cuda_runtime.h>
#include <cstdint>

// Problem constants
#define BSZ 128
#define SDIM 1024
#define AD 128
#define HH 512
#define OUT_T 513

// Grid/tiling
#define NCTA 128
#define NTHREADS 256
#define CLUSTER 4
#define MT 32
#define NT 32

// SMEM word offsets.
// x quarter q (k 256q..256q+255): words [q*8192, q*8192+8192)
//   lo half [0,4096): k = 256q + o*8 + c ; hi half [4096,8192): k = +4
// U region: words [32768, 36864) = half0 2048 | half1 2048
#define UREG 32768
#define REDO 36864
#define RED_STRIDE 40
#define RED_W (8 * 16 * RED_STRIDE)   // 5120 words
#define MBAR_W (REDO + RED_W)         // 41984 (byte off 167936, 8B aligned)
#define SMEM_BYTES ((MBAR_W + 12) * 4)

// Global sync state (zero-init once; epochs monotonic across graph replays)
__device__ unsigned g_arrive[NCTA];
__device__ unsigned g_release;
// One flag per 128-B line (R6 lesson: packing them = false sharing).
__device__ __align__(128) unsigned g_flag[4][32][32];

// tf32 state double buffer; per-mt block of 32768 words, laid out so each
// 8192-word slice is a complete k-quarter in smem-identical layout.
__device__ __align__(16) uint32_t g_xbuf[2][4 * 32768];
// tf32 drive [t][mt][half*2048 + o_u*128 + b*4 + c]
__device__ __align__(16) uint32_t g_ubuf[(size_t)HH * 4 * 4096];

__device__ __forceinline__ void grid_barrier(unsigned epoch, int bid, int tid)
{
    __syncthreads();
    if (tid == 0) {
        __threadfence();
        *((volatile unsigned*)&g_arrive[bid]) = epoch;
    }
    if (bid == 0) {
        if (tid < NCTA) {
            while ((int)(*((volatile unsigned*)&g_arrive[tid]) - epoch) < 0) { }
        }
        __syncthreads();
        if (tid == 0) {
            __threadfence();
            *((volatile unsigned*)&g_release) = epoch;
        }
    } else if (tid == 0) {
        while ((int)(*((volatile unsigned*)&g_release) - epoch) < 0) { }
    }
    __syncthreads();
    __threadfence();
}

__device__ __forceinline__ unsigned ld_acq(const unsigned* p)
{
    unsigned v;
    asm volatile("ld.acquire.gpu.global.u32 %0, [%1];" : "=r"(v) : "l"(p) : "memory");
    return v;
}

__device__ __forceinline__ void st_rel(unsigned* p, unsigned v)
{
    asm volatile("st.release.gpu.global.u32 [%0], %1;" :: "l"(p), "r"(v) : "memory");
}

__device__ __forceinline__ uint32_t f2tf32(float v)
{
    uint32_t r;
    asm("cvt.rna.tf32.f32 %0, %1;" : "=r"(r) : "f"(v));
    return r;
}

__device__ __forceinline__ void mma_tf32(float* d,
                                         uint32_t a0, uint32_t a1, uint32_t a2, uint32_t a3,
                                         uint32_t b0, uint32_t b1)
{
    asm volatile("mma.sync.aligned.m16n8k8.row.col.f32.tf32.tf32.f32 "
                 "{%0,%1,%2,%3}, {%4,%5,%6,%7}, {%8,%9}, {%0,%1,%2,%3};"
                 : "+f"(d[0]), "+f"(d[1]), "+f"(d[2]), "+f"(d[3])
                 : "r"(a0), "r"(a1), "r"(a2), "r"(a3), "r"(b0), "r"(b1));
}

__device__ __forceinline__ void bulk_mc(uint32_t dst_smem, const void* src,
                                        uint32_t bytes, uint32_t mbar, uint16_t mask)
{
    asm volatile("cp.async.bulk.shared::cluster.global.mbarrier::complete_tx::bytes"
                 ".multicast::cluster [%0], [%1], %2, [%3], %4;"
                 :: "r"(dst_smem), "l"(src), "r"(bytes), "r"(mbar), "h"(mask)
                 : "memory");
}

__device__ __forceinline__ void mbar_expect(uint32_t mbar, uint32_t bytes)
{
    asm volatile("mbarrier.arrive.expect_tx.shared.b64 _, [%0], %1;"
                 :: "r"(mbar), "r"(bytes) : "memory");
}

__device__ __forceinline__ void mbar_wait(uint32_t mbar, uint32_t parity)
{
    uint32_t done;
    asm volatile("{\n\t.reg .pred p;\n\t"
                 "mbarrier.try_wait.parity.acquire.cta.shared::cta.b64 p, [%1], %2;\n\t"
                 "selp.b32 %0, 1, 0, p;\n\t}"
                 : "=r"(done) : "r"(mbar), "r"(parity) : "memory");
    if (!done) {
        asm volatile("{\n\t.reg .pred P1;\n\t"
                     "W%=:\n\t"
                     "mbarrier.try_wait.parity.acquire.cta.shared::cta.b64 P1, [%0], %1, 0x989680;\n\t"
                     "@P1 bra.uni D%=;\n\t"
                     "bra.uni W%=;\n\t"
                     "D%=:\n\t}"
                     :: "r"(mbar), "r"(parity) : "memory");
    }
}

extern "C" __global__ void __launch_bounds__(NTHREADS, 1) __cluster_dims__(CLUSTER, 1, 1)
ssm_v7_kernel(const float* __restrict__ x0, const float* __restrict__ u,
              const float* __restrict__ A, const float* __restrict__ Bm,
              float* __restrict__ out)
{
    extern __shared__ uint32_t sm[];
    float* red = (float*)(sm + REDO);

    const int tid = threadIdx.x;
    const int bid = blockIdx.x;
    const int mt = bid >> 5;          // cluster ranks share mt (consecutive bids)
    const int nt = bid & 31;
    const int m0 = mt * MT;
    const int n0 = nt * NT;
    const int w = tid >> 5;
    const int lane = tid & 31;
    const int g = lane >> 2;          // 0..7
    const int c = lane & 3;           // 0..3
    const int ss = w & 1;             // s-strip
    const int kg = w >> 1;            // k-group 0..3 (k quarter)
    const int gtid = bid * NTHREADS + tid;

    uint32_t rank;
    asm("mov.u32 %0, %%cluster_ctarank;" : "=r"(rank));

    const uint32_t smb = (uint32_t)__cvta_generic_to_shared(sm);
    const uint32_t mbar0 = smb + MBAR_W * 4;   // mbar[q] = mbar0 + 8q
    const uint32_t mbarU = mbar0 + 32;

    const unsigned base = *((volatile unsigned*)&g_release);

    if (tid == 0) {
#pragma unroll
        for (int q = 0; q < 4; q++)
            asm volatile("mbarrier.init.shared.b64 [%0], %1;"
                         :: "r"(mbar0 + q * 8), "r"(1) : "memory");
        asm volatile("mbarrier.init.shared.b64 [%0], %1;" :: "r"(mbarU), "r"(1) : "memory");
    }
    __syncthreads();
    asm volatile("barrier.cluster.arrive.aligned;" ::: "memory");
    asm volatile("barrier.cluster.wait.aligned;" ::: "memory");

    // expects for t=0 (posted before the global init barrier)
    if (tid < 4) mbar_expect(mbar0 + tid * 8, 32768);
    if (tid == 4) mbar_expect(mbarU, 16384);

    // ---- init: u -> tf32 ubuf [t][mt][half][o_u][b][4] ----
    for (int j = gtid; j < HH * BSZ * (AD / 4); j += NCTA * NTHREADS) {
        int a4 = j & 31;
        int b = (j >> 5) & 127;
        int t = j >> 12;
        float4 v = *(const float4*)(u + ((size_t)b * HH + t) * AD + a4 * 4);
        uint4 o4 = make_uint4(f2tf32(v.x), f2tf32(v.y), f2tf32(v.z), f2tf32(v.w));
        int umt = b >> 5, bl = b & 31;
        size_t widx = ((size_t)t * 4 + umt) * 4096 + (size_t)(a4 & 1) * 2048
                    + (size_t)(a4 >> 1) * 128 + (size_t)bl * 4;
        *(uint4*)(g_ubuf + widx) = o4;
    }
    // ---- init: xbuf[0] = tf32(x0) in quartered layout; out[:,0,:] = x0 ----
    for (int j = gtid; j < BSZ * (SDIM / 4); j += NCTA * NTHREADS) {
        int K4 = j & 255;             // 4-float chunk within s (k = 4*K4)
        int b = j >> 8;
        float4 v = ((const float4*)x0)[j];
        ((float4*)out)[(size_t)b * OUT_T * (SDIM / 4) + K4] = v;
        uint4 o4 = make_uint4(f2tf32(v.x), f2tf32(v.y), f2tf32(v.z), f2tf32(v.w));
        int xmt = b >> 5, bl = b & 31;
        int q = K4 >> 6;                      // k quarter
        int oloc = (K4 & 63) >> 1;            // octet within quarter
        int hi = K4 & 1;
        size_t widx = (size_t)xmt * 32768 + (size_t)q * 8192 + (size_t)hi * 4096
                    + (size_t)oloc * 128 + (size_t)bl * 4;
        *(uint4*)(g_xbuf[0] + widx) = o4;
    }

    // ---- weights into registers (invariant across all 512 steps) ----
    uint32_t a[36][4];
    {
        const int srow = n0 + ss * 16 + g;
#pragma unroll
        for (int i = 0; i < 32; i++) {          // x octets: k = kg*256 + i*8 + {c, c+4}
            int k0 = kg * 256 + i * 8 + c;
            a[i][0] = f2tf32(A[(size_t)srow * SDIM + k0]);
            a[i][1] = f2tf32(A[(size_t)(srow + 8) * SDIM + k0]);
            a[i][2] = f2tf32(A[(size_t)srow * SDIM + k0 + 4]);
            a[i][3] = f2tf32(A[(size_t)(srow + 8) * SDIM + k0 + 4]);
        }
#pragma unroll
        for (int jq = 0; jq < 4; jq++) {        // u octets: k_u = kg*32 + jq*8 + {c, c+4}
            int k0 = (kg * 4 + jq) * 8 + c;
            a[32 + jq][0] = f2tf32(Bm[(size_t)srow * AD + k0]);
            a[32 + jq][1] = f2tf32(Bm[(size_t)(srow + 8) * AD + k0]);
            a[32 + jq][2] = f2tf32(Bm[(size_t)srow * AD + k0 + 4]);
            a[32 + jq][3] = f2tf32(Bm[(size_t)(srow + 8) * AD + k0 + 4]);
        }
    }

    grid_barrier(base + 1, bid, tid);   // init fence (global, once)

    // ---- t=0 staging (no flag dependency; x0 staged by init) ----
    if (tid == 0) {
        const uint32_t* xsrc = g_xbuf[0] + (size_t)mt * 32768 + (size_t)rank * 8192;
        bulk_mc(smb + rank * 32768u, xsrc, 32768, mbar0 + rank * 8, 0xF);
        if (rank < 2) {
            const uint32_t* usrc = g_ubuf + (size_t)mt * 4096 + (size_t)rank * 2048;
            bulk_mc(smb + UREG * 4u + rank * 8192u, usrc, 8192, mbarU, 0xF);
        }
    }

    for (int t = 0; t < HH; t++) {
        // ---- MMA: warp kg starts as soon as ITS 32KB quarter lands ----
        float d[4][4];
#pragma unroll
        for (int nn = 0; nn < 4; nn++)
#pragma unroll
            for (int q = 0; q < 4; q++) d[nn][q] = 0.0f;

        mbar_wait(mbar0 + kg * 8, (uint32_t)(t & 1));
        {
            const uint32_t* xs = sm + kg * 8192 + g * 4 + c;
#pragma unroll
            for (int i = 0; i < 32; i++) {
#pragma unroll
                for (int nn = 0; nn < 4; nn++) {
                    uint32_t blo = xs[i * 128 + nn * 32];
                    uint32_t bhi = xs[i * 128 + nn * 32 + 4096];
                    mma_tf32(d[nn], a[i][0], a[i][1], a[i][2], a[i][3], blo, bhi);
                }
            }
        }
        mbar_wait(mbarU, (uint32_t)(t & 1));
        {
            const uint32_t* us = sm + UREG + kg * 4 * 128 + g * 4 + c;
#pragma unroll
            for (int jq = 0; jq < 4; jq++) {
#pragma unroll
                for (int nn = 0; nn < 4; nn++) {
                    uint32_t blo = us[jq * 128 + nn * 32];
                    uint32_t bhi = us[jq * 128 + nn * 32 + 2048];
                    mma_tf32(d[nn], a[32 + jq][0], a[32 + jq][1],
                             a[32 + jq][2], a[32 + jq][3], blo, bhi);
                }
            }
        }

        // ---- partials to smem ----
        {
            int rb = w * (16 * RED_STRIDE) + g * RED_STRIDE + 2 * c;
#pragma unroll
            for (int nn = 0; nn < 4; nn++) {
                *(float2*)(red + rb + nn * 8) = make_float2(d[nn][0], d[nn][1]);
                *(float2*)(red + rb + 8 * RED_STRIDE + nn * 8) = make_float2(d[nn][2], d[nn][3]);
            }
        }
        __syncthreads();

        // ---- reduce 4 k-partials; write fp32 out + tf32 xbuf ----
        {
            int b = tid >> 3;
            int s4 = (tid & 7) * 4;
            int ssr = s4 >> 4;
            float acc0 = 0.f, acc1 = 0.f, acc2 = 0.f, acc3 = 0.f;
#pragma unroll
            for (int kk = 0; kk < 4; kk++) {
                int wb = (kk * 2 + ssr) * (16 * RED_STRIDE) + b;
                acc0 += red[wb + ((s4 + 0) & 15) * RED_STRIDE];
                acc1 += red[wb + ((s4 + 1) & 15) * RED_STRIDE];
                acc2 += red[wb + ((s4 + 2) & 15) * RED_STRIDE];
                acc3 += red[wb + ((s4 + 3) & 15) * RED_STRIDE];
            }
            float* op = out + ((size_t)(m0 + b) * OUT_T + (t + 1)) * SDIM + n0 + s4;
            *(float4*)op = make_float4(acc0, acc1, acc2, acc3);

            int K4 = (n0 + s4) >> 2;
            int q = K4 >> 6;
            int oloc = (K4 & 63) >> 1;
            int hi = K4 & 1;
            size_t widx = (size_t)mt * 32768 + (size_t)q * 8192 + (size_t)hi * 4096
                        + (size_t)oloc * 128 + (size_t)b * 4;
            uint32_t* xp = g_xbuf[(t + 1) & 1] + widx;
            uint32_t t0 = f2tf32(acc0), t1 = f2tf32(acc1), t2 = f2tf32(acc2), t3 = f2tf32(acc3);
            asm volatile("st.global.cg.v4.b32 [%0], {%1,%2,%3,%4};"
                         :: "l"(xp), "r"(t0), "r"(t1), "r"(t2), "r"(t3) : "memory");
        }
        __syncthreads();

        // ---- publish: single release store (replaces 256x threadfence) ----
        if (tid == 0) st_rel(&g_flag[mt][nt][0], base + 2 + t);

        if (t + 1 < HH) {
            // expects for next phase (local warps already passed their waits)
            if (tid < 4) mbar_expect(mbar0 + tid * 8, 32768);
            if (tid == 4) mbar_expect(mbarU, 16384);
            // smem free + expects posted across the cluster
            asm volatile("barrier.cluster.arrive.aligned;" ::: "memory");
            asm volatile("barrier.cluster.wait.aligned;" ::: "memory");

            if (tid == 0) {
                // quarter `rank` needs only producers nt' = 8*rank..8*rank+7
                unsigned want = base + 2 + t;
#pragma unroll
                for (int j = 0; j < 8; j++) {
                    const unsigned* fp = &g_flag[mt][rank * 8 + j][0];
                    while ((int)(ld_acq(fp) - want) < 0) { }
                }
                const uint32_t* xsrc = g_xbuf[(t + 1) & 1]
                                     + (size_t)mt * 32768 + (size_t)rank * 8192;
                bulk_mc(smb + rank * 32768u, xsrc, 32768, mbar0 + rank * 8, 0xF);
                if (rank < 2) {
                    const uint32_t* usrc = g_ubuf + ((size_t)(t + 1) * 4 + mt) * 4096
                                         + (size_t)rank * 2048;
                    bulk_mc(smb + UREG * 4u + rank * 8192u, usrc, 8192, mbarU, 0xF);
                }
            }
        }
    }

    // Bump the epoch stream past all flag epochs for the next graph replay.
    if (bid == 0 && tid == 0) {
        __threadfence();
        *((volatile unsigned*)&g_release) = base + HH + 2;
    }
}

extern "C" void kernel_launch(void* const* d_in, const int* in_sizes, int n_in,
                              void* d_out, int out_size)
{
    const float* x0 = (const float*)d_in[0];
    const float* u  = (const float*)d_in[1];
    const float* A  = (const float*)d_in[2];
    const float* Bm = (const float*)d_in[3];
    float* out = (float*)d_out;

    cudaFuncSetAttribute(ssm_v7_kernel,
                         cudaFuncAttributeMaxDynamicSharedMemorySize, SMEM_BYTES);

    ssm_v7_kernel<<<NCTA, NTHREADS, SMEM_BYTES>>>(x0, u, A, Bm, out);
}

// round 9
// speedup vs baseline: 1.4731x; 1.4731x over previous
#include <cuda_runtime.h>
#include <cstdint>

// Problem constants
#define BSZ 128
#define SDIM 1024
#define AD 128
#define HH 512
#define OUT_T 513

// Grid/tiling
#define NCTA 128
#define NTHREADS 256
#define CLUSTER 4
#define MT 32
#define NT 32

// SMEM word offsets.
// x quarter q (k 256q..256q+255): words [q*8192, (q+1)*8192)
//   lo half: k = 256q + o*8 + {0..3}; hi half (+4096 words): k = +4
// U region: words [32768, 36864) = half0 2048 | half1 2048
#define UREG 32768
#define REDO 36864
#define RED_STRIDE 40
#define RED_W (8 * 16 * RED_STRIDE)   // 5120 words
#define MBAR_W (REDO + RED_W)         // 41984 (byte off 167936, 8B aligned)
#define SMEM_BYTES ((MBAR_W + 12) * 4)

// Global sync state (zero-init once; epochs monotonic across graph replays)
__device__ unsigned g_arrive[NCTA];
__device__ unsigned g_release;
// One flag per 128-B line (R6 lesson: packing them = false sharing).
__device__ __align__(128) unsigned g_flag[4][32][32];

// tf32 state double buffer; per-mt block of 32768 words; each rank's
// 8192-word slice is a complete k-quarter in smem-identical layout.
__device__ __align__(16) uint32_t g_xbuf[2][4 * 32768];
// tf32 drive [t][mt][half*2048 + o_u*128 + b*4 + c]
__device__ __align__(16) uint32_t g_ubuf[(size_t)HH * 4 * 4096];

__device__ __forceinline__ void grid_barrier(unsigned epoch, int bid, int tid)
{
    __syncthreads();
    if (tid == 0) {
        __threadfence();
        *((volatile unsigned*)&g_arrive[bid]) = epoch;
    }
    if (bid == 0) {
        if (tid < NCTA) {
            while ((int)(*((volatile unsigned*)&g_arrive[tid]) - epoch) < 0) { }
        }
        __syncthreads();
        if (tid == 0) {
            __threadfence();
            *((volatile unsigned*)&g_release) = epoch;
        }
    } else if (tid == 0) {
        while ((int)(*((volatile unsigned*)&g_release) - epoch) < 0) { }
    }
    __syncthreads();
    __threadfence();
}

// 32-CTA group flag barrier (v6 structure): 32 PARALLEL pollers, padded
// flags, single release fence by tid0 (not 256 threadfences).
__device__ __forceinline__ void group_barrier(unsigned epoch, int mt_, int nt_, int tid)
{
    __syncthreads();
    if (tid == 0) {
        asm volatile("fence.acq_rel.gpu;" ::: "memory");
        *((volatile unsigned*)&g_flag[mt_][nt_][0]) = epoch;
    }
    if (tid < 32) {
        while ((int)(*((volatile unsigned*)&g_flag[mt_][tid][0]) - epoch) < 0) { }
    }
    __syncthreads();
    asm volatile("fence.acq_rel.gpu;" ::: "memory");
}

__device__ __forceinline__ uint32_t f2tf32(float v)
{
    uint32_t r;
    asm("cvt.rna.tf32.f32 %0, %1;" : "=r"(r) : "f"(v));
    return r;
}

__device__ __forceinline__ void mma_tf32(float* d,
                                         uint32_t a0, uint32_t a1, uint32_t a2, uint32_t a3,
                                         uint32_t b0, uint32_t b1)
{
    asm volatile("mma.sync.aligned.m16n8k8.row.col.f32.tf32.tf32.f32 "
                 "{%0,%1,%2,%3}, {%4,%5,%6,%7}, {%8,%9}, {%0,%1,%2,%3};"
                 : "+f"(d[0]), "+f"(d[1]), "+f"(d[2]), "+f"(d[3])
                 : "r"(a0), "r"(a1), "r"(a2), "r"(a3), "r"(b0), "r"(b1));
}

__device__ __forceinline__ void bulk_mc(uint32_t dst_smem, const void* src,
                                        uint32_t bytes, uint32_t mbar, uint16_t mask)
{
    asm volatile("cp.async.bulk.shared::cluster.global.mbarrier::complete_tx::bytes"
                 ".multicast::cluster [%0], [%1], %2, [%3], %4;"
                 :: "r"(dst_smem), "l"(src), "r"(bytes), "r"(mbar), "h"(mask)
                 : "memory");
}

__device__ __forceinline__ void mbar_expect(uint32_t mbar, uint32_t bytes)
{
    asm volatile("mbarrier.arrive.expect_tx.shared.b64 _, [%0], %1;"
                 :: "r"(mbar), "r"(bytes) : "memory");
}

__device__ __forceinline__ void mbar_wait(uint32_t mbar, uint32_t parity)
{
    uint32_t done;
    asm volatile("{\n\t.reg .pred p;\n\t"
                 "mbarrier.try_wait.parity.acquire.cta.shared::cta.b64 p, [%1], %2;\n\t"
                 "selp.b32 %0, 1, 0, p;\n\t}"
                 : "=r"(done) : "r"(mbar), "r"(parity) : "memory");
    if (!done) {
        asm volatile("{\n\t.reg .pred P1;\n\t"
                     "W%=:\n\t"
                     "mbarrier.try_wait.parity.acquire.cta.shared::cta.b64 P1, [%0], %1, 0x989680;\n\t"
                     "@P1 bra.uni D%=;\n\t"
                     "bra.uni W%=;\n\t"
                     "D%=:\n\t}"
                     :: "r"(mbar), "r"(parity) : "memory");
    }
}

extern "C" __global__ void __launch_bounds__(NTHREADS, 1) __cluster_dims__(CLUSTER, 1, 1)
ssm_v8_kernel(const float* __restrict__ x0, const float* __restrict__ u,
              const float* __restrict__ A, const float* __restrict__ Bm,
              float* __restrict__ out)
{
    extern __shared__ uint32_t sm[];
    float* red = (float*)(sm + REDO);

    const int tid = threadIdx.x;
    const int bid = blockIdx.x;
    const int mt = bid >> 5;          // cluster ranks share mt (consecutive bids)
    const int nt = bid & 31;
    const int m0 = mt * MT;
    const int n0 = nt * NT;
    const int w = tid >> 5;
    const int lane = tid & 31;
    const int g = lane >> 2;          // 0..7
    const int c = lane & 3;           // 0..3
    const int ss = w & 1;             // s-strip
    const int kg = w >> 1;            // k-group 0..3 (k quarter)
    const int gtid = bid * NTHREADS + tid;

    uint32_t rank;
    asm("mov.u32 %0, %%cluster_ctarank;" : "=r"(rank));

    const uint32_t smb = (uint32_t)__cvta_generic_to_shared(sm);
    const uint32_t mbar0 = smb + MBAR_W * 4;   // mbar[q] = mbar0 + 8q
    const uint32_t mbarU = mbar0 + 32;

    const unsigned base = *((volatile unsigned*)&g_release);

    if (tid == 0) {
#pragma unroll
        for (int q = 0; q < 4; q++)
            asm volatile("mbarrier.init.shared.b64 [%0], %1;"
                         :: "r"(mbar0 + q * 8), "r"(1) : "memory");
        asm volatile("mbarrier.init.shared.b64 [%0], %1;" :: "r"(mbarU), "r"(1) : "memory");
    }
    __syncthreads();
    asm volatile("barrier.cluster.arrive.aligned;" ::: "memory");
    asm volatile("barrier.cluster.wait.aligned;" ::: "memory");

    // ---- init: u -> tf32 ubuf [t][mt][half][o_u][b][4] ----
    for (int j = gtid; j < HH * BSZ * (AD / 4); j += NCTA * NTHREADS) {
        int a4 = j & 31;
        int b = (j >> 5) & 127;
        int t = j >> 12;
        float4 v = *(const float4*)(u + ((size_t)b * HH + t) * AD + a4 * 4);
        uint4 o4 = make_uint4(f2tf32(v.x), f2tf32(v.y), f2tf32(v.z), f2tf32(v.w));
        int umt = b >> 5, bl = b & 31;
        size_t widx = ((size_t)t * 4 + umt) * 4096 + (size_t)(a4 & 1) * 2048
                    + (size_t)(a4 >> 1) * 128 + (size_t)bl * 4;
        *(uint4*)(g_ubuf + widx) = o4;
    }
    // ---- init: xbuf[0] = tf32(x0) in quartered layout; out[:,0,:] = x0 ----
    for (int j = gtid; j < BSZ * (SDIM / 4); j += NCTA * NTHREADS) {
        int K4 = j & 255;             // 4-float chunk within s (k = 4*K4)
        int b = j >> 8;
        float4 v = ((const float4*)x0)[j];
        ((float4*)out)[(size_t)b * OUT_T * (SDIM / 4) + K4] = v;
        uint4 o4 = make_uint4(f2tf32(v.x), f2tf32(v.y), f2tf32(v.z), f2tf32(v.w));
        int xmt = b >> 5, bl = b & 31;
        int q = K4 >> 6;                      // k quarter
        int oloc = (K4 & 63) >> 1;            // octet within quarter
        int hi = K4 & 1;
        size_t widx = (size_t)xmt * 32768 + (size_t)q * 8192 + (size_t)hi * 4096
                    + (size_t)oloc * 128 + (size_t)bl * 4;
        *(uint4*)(g_xbuf[0] + widx) = o4;
    }

    // ---- weights into registers (invariant across all 512 steps) ----
    uint32_t a[36][4];
    {
        const int srow = n0 + ss * 16 + g;
#pragma unroll
        for (int i = 0; i < 32; i++) {          // x octets: k = kg*256 + i*8 + {c, c+4}
            int k0 = kg * 256 + i * 8 + c;
            a[i][0] = f2tf32(A[(size_t)srow * SDIM + k0]);
            a[i][1] = f2tf32(A[(size_t)(srow + 8) * SDIM + k0]);
            a[i][2] = f2tf32(A[(size_t)srow * SDIM + k0 + 4]);
            a[i][3] = f2tf32(A[(size_t)(srow + 8) * SDIM + k0 + 4]);
        }
#pragma unroll
        for (int jq = 0; jq < 4; jq++) {        // u octets: k_u = kg*32 + jq*8 + {c, c+4}
            int k0 = (kg * 4 + jq) * 8 + c;
            a[32 + jq][0] = f2tf32(Bm[(size_t)srow * AD + k0]);
            a[32 + jq][1] = f2tf32(Bm[(size_t)(srow + 8) * AD + k0]);
            a[32 + jq][2] = f2tf32(Bm[(size_t)srow * AD + k0 + 4]);
            a[32 + jq][3] = f2tf32(Bm[(size_t)(srow + 8) * AD + k0 + 4]);
        }
    }

    grid_barrier(base + 1, bid, tid);   // init fence (global, once)

    for (int t = 0; t < HH; t++) {
        // ---- stage (v6 structure): tid0 posts expects + issues DMAs ----
        if (tid == 0) {
#pragma unroll
            for (int q = 0; q < 4; q++) mbar_expect(mbar0 + q * 8, 32768);
            mbar_expect(mbarU, 16384);
            // rank r copies its complete k-quarter (32KB, layout-identical)
            const uint32_t* xsrc = g_xbuf[t & 1] + (size_t)mt * 32768 + (size_t)rank * 8192;
            bulk_mc(smb + rank * 32768u, xsrc, 32768, mbar0 + rank * 8, 0xF);
            if (rank >= 2) {
                const uint32_t* usrc = g_ubuf + ((size_t)t * 4 + mt) * 4096
                                     + (size_t)(rank - 2) * 2048;
                bulk_mc(smb + UREG * 4u + (rank - 2) * 8192u, usrc, 8192, mbarU, 0xF);
            }
        }

        // ---- MMA: warp kg starts as soon as ITS quarter lands ----
        float d[4][4];
#pragma unroll
        for (int nn = 0; nn < 4; nn++)
#pragma unroll
            for (int q = 0; q < 4; q++) d[nn][q] = 0.0f;

        mbar_wait(mbar0 + kg * 8, (uint32_t)(t & 1));
        {
            const uint32_t* xs = sm + kg * 8192 + g * 4 + c;
#pragma unroll
            for (int i = 0; i < 32; i++) {
#pragma unroll
                for (int nn = 0; nn < 4; nn++) {
                    uint32_t blo = xs[i * 128 + nn * 32];
                    uint32_t bhi = xs[i * 128 + nn * 32 + 4096];
                    mma_tf32(d[nn], a[i][0], a[i][1], a[i][2], a[i][3], blo, bhi);
                }
            }
        }
        mbar_wait(mbarU, (uint32_t)(t & 1));
        {
            const uint32_t* us = sm + UREG + kg * 4 * 128 + g * 4 + c;
#pragma unroll
            for (int jq = 0; jq < 4; jq++) {
#pragma unroll
                for (int nn = 0; nn < 4; nn++) {
                    uint32_t blo = us[jq * 128 + nn * 32];
                    uint32_t bhi = us[jq * 128 + nn * 32 + 2048];
                    mma_tf32(d[nn], a[32 + jq][0], a[32 + jq][1],
                             a[32 + jq][2], a[32 + jq][3], blo, bhi);
                }
            }
        }

        // ---- partials to smem ----
        {
            int rb = w * (16 * RED_STRIDE) + g * RED_STRIDE + 2 * c;
#pragma unroll
            for (int nn = 0; nn < 4; nn++) {
                *(float2*)(red + rb + nn * 8) = make_float2(d[nn][0], d[nn][1]);
                *(float2*)(red + rb + 8 * RED_STRIDE + nn * 8) = make_float2(d[nn][2], d[nn][3]);
            }
        }
        __syncthreads();

        // ---- reduce 4 k-partials; write fp32 out + tf32 xbuf ----
        {
            int b = tid >> 3;
            int s4 = (tid & 7) * 4;
            int ssr = s4 >> 4;
            float acc0 = 0.f, acc1 = 0.f, acc2 = 0.f, acc3 = 0.f;
#pragma unroll
            for (int kk = 0; kk < 4; kk++) {
                int wb = (kk * 2 + ssr) * (16 * RED_STRIDE) + b;
                acc0 += red[wb + ((s4 + 0) & 15) * RED_STRIDE];
                acc1 += red[wb + ((s4 + 1) & 15) * RED_STRIDE];
                acc2 += red[wb + ((s4 + 2) & 15) * RED_STRIDE];
                acc3 += red[wb + ((s4 + 3) & 15) * RED_STRIDE];
            }
            float* op = out + ((size_t)(m0 + b) * OUT_T + (t + 1)) * SDIM + n0 + s4;
            *(float4*)op = make_float4(acc0, acc1, acc2, acc3);

            int K4 = (n0 + s4) >> 2;
            int q = K4 >> 6;
            int oloc = (K4 & 63) >> 1;
            int hi = K4 & 1;
            size_t widx = (size_t)mt * 32768 + (size_t)q * 8192 + (size_t)hi * 4096
                        + (size_t)oloc * 128 + (size_t)b * 4;
            uint32_t* xp = g_xbuf[(t + 1) & 1] + widx;
            uint32_t t0 = f2tf32(acc0), t1 = f2tf32(acc1), t2 = f2tf32(acc2), t3 = f2tf32(acc3);
            asm volatile("st.global.cg.v4.b32 [%0], {%1,%2,%3,%4};"
                         :: "l"(xp), "r"(t0), "r"(t1), "r"(t2), "r"(t3) : "memory");
        }

        // ---- 32-CTA group barrier (1 global RT, 32 parallel pollers) ----
        group_barrier(base + 2 + t, mt, nt, tid);
    }

    // Bump the epoch stream past all flag epochs for the next graph replay.
    if (bid == 0 && tid == 0) {
        __threadfence();
        *((volatile unsigned*)&g_release) = base + HH + 2;
    }
}

extern "C" void kernel_launch(void* const* d_in, const int* in_sizes, int n_in,
                              void* d_out, int out_size)
{
    const float* x0 = (const float*)d_in[0];
    const float* u  = (const float*)d_in[1];
    const float* A  = (const float*)d_in[2];
    const float* Bm = (const float*)d_in[3];
    float* out = (float*)d_out;

    cudaFuncSetAttribute(ssm_v8_kernel,
                         cudaFuncAttributeMaxDynamicSharedMemorySize, SMEM_BYTES);

    ssm_v8_kernel<<<NCTA, NTHREADS, SMEM_BYTES>>>(x0, u, A, Bm, out);
}

// round 10
// speedup vs baseline: 1.4746x; 1.0010x over previous
#include <cuda_runtime.h>
#include <cstdint>

// Problem constants
#define BSZ 128
#define SDIM 1024
#define AD 128
#define HH 512
#define OUT_T 513

// Grid/tiling
#define NCTA 128
#define NTHREADS 256
#define CLUSTER 4
#define MT 32
#define NT 32

// SMEM word offsets.
// x quarter q (k 256q..256q+255): words [q*8192, (q+1)*8192)
//   lo half: word(k,b) = q*8192 + oloc*128 + b*4 + (k&3), oloc=(k>>3)-32q
//   hi half (+4096): k&4 set
// U region: words [32768, 36864) = half0 2048 | half1 2048
#define UREG 32768
#define REDO 36864
#define RS 34                          // reduce row stride (words)
#define RED_W (8 * 32 * RS)            // 8704 words
#define MBAR_W (REDO + RED_W)          // 45568 (byte off 182272, 8B aligned)
#define SMEM_BYTES ((MBAR_W + 12) * 4)

// Global sync state (zero-init once; epochs monotonic across graph replays)
__device__ unsigned g_arrive[NCTA];
__device__ unsigned g_release;
// One flag per 128-B line (R6 lesson: packing them = false sharing).
__device__ __align__(128) unsigned g_flag[4][32][32];

// tf32 state double buffer; per-mt block of 32768 words; quarter q of mt is
// the contiguous 8192-word slice q, smem-layout-identical.
__device__ __align__(16) uint32_t g_xbuf[2][4 * 32768];
// tf32 drive [t][mt][half*2048 + o_u*128 + b*4 + c]
__device__ __align__(16) uint32_t g_ubuf[(size_t)HH * 4 * 4096];

__device__ __forceinline__ void grid_barrier(unsigned epoch, int bid, int tid)
{
    __syncthreads();
    if (tid == 0) {
        __threadfence();
        *((volatile unsigned*)&g_arrive[bid]) = epoch;
    }
    if (bid == 0) {
        if (tid < NCTA) {
            while ((int)(*((volatile unsigned*)&g_arrive[tid]) - epoch) < 0) { }
        }
        __syncthreads();
        if (tid == 0) {
            __threadfence();
            *((volatile unsigned*)&g_release) = epoch;
        }
    } else if (tid == 0) {
        while ((int)(*((volatile unsigned*)&g_release) - epoch) < 0) { }
    }
    __syncthreads();
    __threadfence();
}

__device__ __forceinline__ uint32_t f2tf32(float v)
{
    uint32_t r;
    asm("cvt.rna.tf32.f32 %0, %1;" : "=r"(r) : "f"(v));
    return r;
}

__device__ __forceinline__ void mma_tf32(float* d,
                                         uint32_t a0, uint32_t a1, uint32_t a2, uint32_t a3,
                                         uint32_t b0, uint32_t b1)
{
    asm volatile("mma.sync.aligned.m16n8k8.row.col.f32.tf32.tf32.f32 "
                 "{%0,%1,%2,%3}, {%4,%5,%6,%7}, {%8,%9}, {%0,%1,%2,%3};"
                 : "+f"(d[0]), "+f"(d[1]), "+f"(d[2]), "+f"(d[3])
                 : "r"(a0), "r"(a1), "r"(a2), "r"(a3), "r"(b0), "r"(b1));
}

__device__ __forceinline__ void bulk_mc(uint32_t dst_smem, const void* src,
                                        uint32_t bytes, uint32_t mbar, uint16_t mask)
{
    asm volatile("cp.async.bulk.shared::cluster.global.mbarrier::complete_tx::bytes"
                 ".multicast::cluster [%0], [%1], %2, [%3], %4;"
                 :: "r"(dst_smem), "l"(src), "r"(bytes), "r"(mbar), "h"(mask)
                 : "memory");
}

__device__ __forceinline__ void mbar_expect(uint32_t mbar, uint32_t bytes)
{
    asm volatile("mbarrier.arrive.expect_tx.shared.b64 _, [%0], %1;"
                 :: "r"(mbar), "r"(bytes) : "memory");
}

__device__ __forceinline__ void mbar_wait(uint32_t mbar, uint32_t parity)
{
    uint32_t done;
    asm volatile("{\n\t.reg .pred p;\n\t"
                 "mbarrier.try_wait.parity.acquire.cta.shared::cta.b64 p, [%1], %2;\n\t"
                 "selp.b32 %0, 1, 0, p;\n\t}"
                 : "=r"(done) : "r"(mbar), "r"(parity) : "memory");
    if (!done) {
        asm volatile("{\n\t.reg .pred P1;\n\t"
                     "W%=:\n\t"
                     "mbarrier.try_wait.parity.acquire.cta.shared::cta.b64 P1, [%0], %1, 0x989680;\n\t"
                     "@P1 bra.uni D%=;\n\t"
                     "bra.uni W%=;\n\t"
                     "D%=:\n\t}"
                     :: "r"(mbar), "r"(parity) : "memory");
    }
}

__device__ __forceinline__ void poll_flag(const unsigned* fp, unsigned want)
{
    while ((int)(*((volatile const unsigned*)fp) - want) < 0) { }
}

extern "C" __global__ void __launch_bounds__(NTHREADS, 1) __cluster_dims__(CLUSTER, 1, 1)
ssm_v9_kernel(const float* __restrict__ x0, const float* __restrict__ u,
              const float* __restrict__ A, const float* __restrict__ Bm,
              float* __restrict__ out)
{
    extern __shared__ uint32_t sm[];
    float* red = (float*)(sm + REDO);

    const int tid = threadIdx.x;
    const int bid = blockIdx.x;
    const int mt = bid >> 5;          // cluster ranks share mt (consecutive bids)
    const int nt = bid & 31;
    const int ntc = nt & ~3;          // cluster base within group
    const int m0 = mt * MT;
    const int n0 = nt * NT;
    const int w = tid >> 5;           // warp = k-slice 0..7
    const int lane = tid & 31;
    const int g = lane >> 2;          // 0..7
    const int c = lane & 3;           // 0..3
    const int q = w >> 1;             // x quarter this warp consumes
    const int gtid = bid * NTHREADS + tid;

    uint32_t rank;
    asm("mov.u32 %0, %%cluster_ctarank;" : "=r"(rank));

    const uint32_t smb = (uint32_t)__cvta_generic_to_shared(sm);
    const uint32_t mbar0 = smb + MBAR_W * 4;   // mbar[q] = mbar0 + 8q
    const uint32_t mbarU = mbar0 + 32;

    const unsigned base = *((volatile unsigned*)&g_release);

    if (tid == 0) {
#pragma unroll
        for (int qq = 0; qq < 4; qq++)
            asm volatile("mbarrier.init.shared.b64 [%0], %1;"
                         :: "r"(mbar0 + qq * 8), "r"(1) : "memory");
        asm volatile("mbarrier.init.shared.b64 [%0], %1;" :: "r"(mbarU), "r"(1) : "memory");
    }
    __syncthreads();
    asm volatile("barrier.cluster.arrive.aligned;" ::: "memory");
    asm volatile("barrier.cluster.wait.aligned;" ::: "memory");

    // ---- init: u -> tf32 ubuf [t][mt][half][o_u][b][4] ----
    for (int j = gtid; j < HH * BSZ * (AD / 4); j += NCTA * NTHREADS) {
        int a4 = j & 31;
        int b = (j >> 5) & 127;
        int t = j >> 12;
        float4 v = *(const float4*)(u + ((size_t)b * HH + t) * AD + a4 * 4);
        uint4 o4 = make_uint4(f2tf32(v.x), f2tf32(v.y), f2tf32(v.z), f2tf32(v.w));
        int umt = b >> 5, bl = b & 31;
        size_t widx = ((size_t)t * 4 + umt) * 4096 + (size_t)(a4 & 1) * 2048
                    + (size_t)(a4 >> 1) * 128 + (size_t)bl * 4;
        *(uint4*)(g_ubuf + widx) = o4;
    }
    // ---- init: xbuf[0] = tf32(x0) in quartered layout; out[:,0,:] = x0 ----
    for (int j = gtid; j < BSZ * (SDIM / 4); j += NCTA * NTHREADS) {
        int K4 = j & 255;             // 4-float chunk within s (k = 4*K4)
        int b = j >> 8;
        float4 v = ((const float4*)x0)[j];
        ((float4*)out)[(size_t)b * OUT_T * (SDIM / 4) + K4] = v;
        uint4 o4 = make_uint4(f2tf32(v.x), f2tf32(v.y), f2tf32(v.z), f2tf32(v.w));
        int xmt = b >> 5, bl = b & 31;
        int qq = K4 >> 6;                     // k quarter
        int oloc = (K4 & 63) >> 1;            // octet within quarter
        int hi = K4 & 1;
        size_t widx = (size_t)xmt * 32768 + (size_t)qq * 8192 + (size_t)hi * 4096
                    + (size_t)oloc * 128 + (size_t)bl * 4;
        *(uint4*)(g_xbuf[0] + widx) = o4;
    }

    // ---- weights into registers: warp w = k-slice, BOTH s-strips ----
    // x: 16 octets (global o = q*32 + (w&1)*16 + i); u: 2 octets (o_u = 2w+jq)
    uint32_t ax[2][16][4];
    uint32_t au[2][2][4];
    {
#pragma unroll
        for (int ss = 0; ss < 2; ss++) {
            const int srow = n0 + ss * 16 + g;
#pragma unroll
            for (int i = 0; i < 16; i++) {
                int k0 = (q * 32 + (w & 1) * 16 + i) * 8 + c;
                ax[ss][i][0] = f2tf32(A[(size_t)srow * SDIM + k0]);
                ax[ss][i][1] = f2tf32(A[(size_t)(srow + 8) * SDIM + k0]);
                ax[ss][i][2] = f2tf32(A[(size_t)srow * SDIM + k0 + 4]);
                ax[ss][i][3] = f2tf32(A[(size_t)(srow + 8) * SDIM + k0 + 4]);
            }
#pragma unroll
            for (int jq = 0; jq < 2; jq++) {
                int k0 = (2 * w + jq) * 8 + c;
                au[ss][jq][0] = f2tf32(Bm[(size_t)srow * AD + k0]);
                au[ss][jq][1] = f2tf32(Bm[(size_t)(srow + 8) * AD + k0]);
                au[ss][jq][2] = f2tf32(Bm[(size_t)srow * AD + k0 + 4]);
                au[ss][jq][3] = f2tf32(Bm[(size_t)(srow + 8) * AD + k0 + 4]);
            }
        }
    }

    grid_barrier(base + 1, bid, tid);   // init fence (global, once)

    // ---- t=0 staging: no flag deps; rank r DMAs its whole quarter ----
    if (tid == 0) {
        asm volatile("fence.proxy.async;" ::: "memory");
        bulk_mc(smb + rank * 32768u,
                g_xbuf[0] + (size_t)mt * 32768 + (size_t)rank * 8192,
                32768, mbar0 + rank * 8, 0xF);
        if (rank == 0)
            bulk_mc(smb + UREG * 4u, g_ubuf + (size_t)mt * 4096, 16384, mbarU, 0xF);
    }

    for (int t = 0; t < HH; t++) {
        // ---- expects (lane 1 of warps 0..4) ----
        if (lane == 1) {
            if (w < 4) mbar_expect(mbar0 + w * 8, 32768);
            else if (w == 4) mbar_expect(mbarU, 16384);
        }
        // ---- fine-grained stage: lane 0 of warp w handles producer rank*8+w ----
        if (lane == 0 && t > 0) {
            unsigned want = base + 1 + t;   // flags of step t-1
            // peers' reads of step t-1 smem must be done before overwrite
#pragma unroll
            for (int p = 0; p < 4; p++) {
                if (p != (int)rank) poll_flag(&g_flag[mt][ntc + p][0], want);
            }
            if (w == 0 && rank == 0) {
                asm volatile("fence.proxy.async;" ::: "memory");
                bulk_mc(smb + UREG * 4u,
                        g_ubuf + ((size_t)t * 4 + mt) * 4096, 16384, mbarU, 0xF);
            }
            poll_flag(&g_flag[mt][rank * 8 + w][0], want);
            asm volatile("fence.proxy.async;" ::: "memory");
            // producer j=w of quarter `rank`: two 2KB chunks (lo/hi halves)
            const uint32_t* srcb = g_xbuf[t & 1] + (size_t)mt * 32768
                                 + (size_t)rank * 8192 + (size_t)w * 512;
            uint32_t dstb = smb + (rank * 8192u + w * 512u) * 4u;
            bulk_mc(dstb, srcb, 2048, mbar0 + rank * 8, 0xF);
            bulk_mc(dstb + 4096u * 4u, srcb + 4096, 2048, mbar0 + rank * 8, 0xF);
        }

        // ---- MMA: warp w waits only on its quarter, computes both s-strips ----
        float d[2][4][4];
#pragma unroll
        for (int ss = 0; ss < 2; ss++)
#pragma unroll
            for (int nn = 0; nn < 4; nn++)
#pragma unroll
                for (int e = 0; e < 4; e++) d[ss][nn][e] = 0.0f;

        mbar_wait(mbar0 + q * 8, (uint32_t)(t & 1));
        {
            const uint32_t* xs = sm + q * 8192 + (w & 1) * 16 * 128 + g * 4 + c;
#pragma unroll
            for (int i = 0; i < 16; i++) {
#pragma unroll
                for (int nn = 0; nn < 4; nn++) {
                    uint32_t blo = xs[i * 128 + nn * 32];
                    uint32_t bhi = xs[i * 128 + nn * 32 + 4096];
                    mma_tf32(d[0][nn], ax[0][i][0], ax[0][i][1], ax[0][i][2], ax[0][i][3], blo, bhi);
                    mma_tf32(d[1][nn], ax[1][i][0], ax[1][i][1], ax[1][i][2], ax[1][i][3], blo, bhi);
                }
            }
        }
        mbar_wait(mbarU, (uint32_t)(t & 1));
        {
            const uint32_t* us = sm + UREG + 2 * w * 128 + g * 4 + c;
#pragma unroll
            for (int jq = 0; jq < 2; jq++) {
#pragma unroll
                for (int nn = 0; nn < 4; nn++) {
                    uint32_t blo = us[jq * 128 + nn * 32];
                    uint32_t bhi = us[jq * 128 + nn * 32 + 2048];
                    mma_tf32(d[0][nn], au[0][jq][0], au[0][jq][1], au[0][jq][2], au[0][jq][3], blo, bhi);
                    mma_tf32(d[1][nn], au[1][jq][0], au[1][jq][1], au[1][jq][2], au[1][jq][3], blo, bhi);
                }
            }
        }

        // ---- partials to smem: red[w][srow 0..31][b 0..31], stride RS ----
        {
            float* rb = red + w * (32 * RS);
#pragma unroll
            for (int ss = 0; ss < 2; ss++) {
                int r0 = ss * 16 + g;
#pragma unroll
                for (int nn = 0; nn < 4; nn++) {
                    int cb = nn * 8 + 2 * c;
                    *(float2*)(rb + r0 * RS + cb) = make_float2(d[ss][nn][0], d[ss][nn][1]);
                    *(float2*)(rb + (r0 + 8) * RS + cb) = make_float2(d[ss][nn][2], d[ss][nn][3]);
                }
            }
        }
        __syncthreads();

        // ---- reduce 8 k-partials; write fp32 out + tf32 xbuf ----
        {
            int b = tid >> 3;
            int s4 = (tid & 7) * 4;
            float acc0 = 0.f, acc1 = 0.f, acc2 = 0.f, acc3 = 0.f;
#pragma unroll
            for (int kk = 0; kk < 8; kk++) {
                const float* rb = red + kk * (32 * RS) + b;
                acc0 += rb[(s4 + 0) * RS];
                acc1 += rb[(s4 + 1) * RS];
                acc2 += rb[(s4 + 2) * RS];
                acc3 += rb[(s4 + 3) * RS];
            }
            float* op = out + ((size_t)(m0 + b) * OUT_T + (t + 1)) * SDIM + n0 + s4;
            *(float4*)op = make_float4(acc0, acc1, acc2, acc3);

            int K4 = (n0 + s4) >> 2;
            int qq = K4 >> 6;
            int oloc = (K4 & 63) >> 1;
            int hi = K4 & 1;
            size_t widx = (size_t)mt * 32768 + (size_t)qq * 8192 + (size_t)hi * 4096
                        + (size_t)oloc * 128 + (size_t)b * 4;
            uint32_t* xp = g_xbuf[(t + 1) & 1] + widx;
            uint32_t t0 = f2tf32(acc0), t1 = f2tf32(acc1), t2 = f2tf32(acc2), t3 = f2tf32(acc3);
            asm volatile("st.global.cg.v4.b32 [%0], {%1,%2,%3,%4};"
                         :: "l"(xp), "r"(t0), "r"(t1), "r"(t2), "r"(t3) : "memory");
        }
        __syncthreads();

        // ---- publish (single release store; consumers poll fine-grained) ----
        if (tid == 0) {
            asm volatile("fence.acq_rel.gpu;" ::: "memory");
            *((volatile unsigned*)&g_flag[mt][nt][0]) = base + 2 + t;
        }
    }

    // Bump the epoch stream past all flag epochs for the next graph replay.
    if (bid == 0 && tid == 0) {
        __threadfence();
        *((volatile unsigned*)&g_release) = base + HH + 2;
    }
}

extern "C" void kernel_launch(void* const* d_in, const int* in_sizes, int n_in,
                              void* d_out, int out_size)
{
    const float* x0 = (const float*)d_in[0];
    const float* u  = (const float*)d_in[1];
    const float* A  = (const float*)d_in[2];
    const float* Bm = (const float*)d_in[3];
    float* out = (float*)d_out;

    cudaFuncSetAttribute(ssm_v9_kernel,
                         cudaFuncAttributeMaxDynamicSharedMemorySize, SMEM_BYTES);

    ssm_v9_kernel<<<NCTA, NTHREADS, SMEM_BYTES>>>(x0, u, A, Bm, out);
}

// round 11
// speedup vs baseline: 2.1301x; 1.4446x over previous
#include <cuda_runtime.h>
#include <cuda_fp16.h>
#include <cstdint>

// Problem constants
#define BSZ 128
#define SDIM 1024
#define AD 128
#define HH 512
#define OUT_T 513

// Grid/tiling
#define NCTA 128
#define NTHREADS 256
#define CLUSTER 4
#define MT 32
#define NT 32

// SMEM word layout (uint32 = half2). x word(k2, b):
//   o16 = k2>>3 (16-k group), c2 = k2&7
//   idx = o16*128 + b*4 + (c2&3) + ((c2&4) ? 8192 : 0)
// -> lo region [0,8192), hi [8192,16384); quarter q = o16 in [16q,16q+16)
//    occupies lo words [q*2048,+2048) and hi words [8192+q*2048,+2048).
// u region at [16384,18432): idx_u = o16u*128 + b*4 + (c2&3) + ((c2&4)?1024:0)
#define XWORDS 16384
#define XHI 8192
#define UO 16384
#define UHI 1024
#define REDO 18432
#define RED_STRIDE 40
#define RED_W (8 * 16 * RED_STRIDE)    // 5120 words
#define MBAR_W (REDO + RED_W)          // 23552 (byte off 94208, 8B aligned)
#define SMEM_BYTES ((MBAR_W + 12) * 4)

// Global sync state (zero-init once; epochs monotonic across graph replays)
__device__ unsigned g_arrive[NCTA];
__device__ unsigned g_release;
// One flag per 128-B line (R6 lesson: packing them = false sharing).
__device__ __align__(128) unsigned g_flag[4][32][32];

// fp16 state double buffer; per-mt block of 16384 half2 words mirroring smem.
// Rank slice r = contiguous words [r*4096,(r+1)*4096): r0=lo k0..511,
// r1=lo k512..1023, r2=hi k0..511, r3=hi k512..1023.
__device__ __align__(16) uint32_t g_xbuf[2][4 * 16384];
// fp16 drive [t][mt][2048 words], smem-u-layout mirror
__device__ __align__(16) uint32_t g_ubuf[(size_t)HH * 4 * 2048];

__device__ __forceinline__ void grid_barrier(unsigned epoch, int bid, int tid)
{
    __syncthreads();
    if (tid == 0) {
        __threadfence();
        *((volatile unsigned*)&g_arrive[bid]) = epoch;
    }
    if (bid == 0) {
        if (tid < NCTA) {
            while ((int)(*((volatile unsigned*)&g_arrive[tid]) - epoch) < 0) { }
        }
        __syncthreads();
        if (tid == 0) {
            __threadfence();
            *((volatile unsigned*)&g_release) = epoch;
        }
    } else if (tid == 0) {
        while ((int)(*((volatile unsigned*)&g_release) - epoch) < 0) { }
    }
    __syncthreads();
    __threadfence();
}

// 32-CTA group flag barrier (v6 = 2429us structure, verbatim).
__device__ __forceinline__ void group_barrier(unsigned epoch, int mt_, int nt_, int tid)
{
    __threadfence();
    __syncthreads();
    if (tid == 0) {
        *((volatile unsigned*)&g_flag[mt_][nt_][0]) = epoch;
    }
    if (tid < 32) {
        while ((int)(*((volatile unsigned*)&g_flag[mt_][tid][0]) - epoch) < 0) { }
    }
    __syncthreads();
}

__device__ __forceinline__ uint32_t pack2(float x, float y)
{
    __half2 h = __floats2half2_rn(x, y);
    return *(uint32_t*)&h;
}

__device__ __forceinline__ void mma_f16(float* d,
                                        uint32_t a0, uint32_t a1, uint32_t a2, uint32_t a3,
                                        uint32_t b0, uint32_t b1)
{
    asm volatile("mma.sync.aligned.m16n8k16.row.col.f32.f16.f16.f32 "
                 "{%0,%1,%2,%3}, {%4,%5,%6,%7}, {%8,%9}, {%0,%1,%2,%3};"
                 : "+f"(d[0]), "+f"(d[1]), "+f"(d[2]), "+f"(d[3])
                 : "r"(a0), "r"(a1), "r"(a2), "r"(a3), "r"(b0), "r"(b1));
}

__device__ __forceinline__ void bulk_mc(uint32_t dst_smem, const void* src,
                                        uint32_t bytes, uint32_t mbar, uint16_t mask)
{
    asm volatile("cp.async.bulk.shared::cluster.global.mbarrier::complete_tx::bytes"
                 ".multicast::cluster [%0], [%1], %2, [%3], %4;"
                 :: "r"(dst_smem), "l"(src), "r"(bytes), "r"(mbar), "h"(mask)
                 : "memory");
}

__device__ __forceinline__ void mbar_expect(uint32_t mbar, uint32_t bytes)
{
    asm volatile("mbarrier.arrive.expect_tx.shared.b64 _, [%0], %1;"
                 :: "r"(mbar), "r"(bytes) : "memory");
}

__device__ __forceinline__ void mbar_wait(uint32_t mbar, uint32_t parity)
{
    uint32_t done;
    asm volatile("{\n\t.reg .pred p;\n\t"
                 "mbarrier.try_wait.parity.acquire.cta.shared::cta.b64 p, [%1], %2;\n\t"
                 "selp.b32 %0, 1, 0, p;\n\t}"
                 : "=r"(done) : "r"(mbar), "r"(parity) : "memory");
    if (!done) {
        asm volatile("{\n\t.reg .pred P1;\n\t"
                     "W%=:\n\t"
                     "mbarrier.try_wait.parity.acquire.cta.shared::cta.b64 P1, [%0], %1, 0x989680;\n\t"
                     "@P1 bra.uni D%=;\n\t"
                     "bra.uni W%=;\n\t"
                     "D%=:\n\t}"
                     :: "r"(mbar), "r"(parity) : "memory");
    }
}

extern "C" __global__ void __launch_bounds__(NTHREADS, 1) __cluster_dims__(CLUSTER, 1, 1)
ssm_v10_kernel(const float* __restrict__ x0, const float* __restrict__ u,
               const float* __restrict__ A, const float* __restrict__ Bm,
               float* __restrict__ out)
{
    extern __shared__ uint32_t sm[];
    float* red = (float*)(sm + REDO);

    const int tid = threadIdx.x;
    const int bid = blockIdx.x;
    const int mt = bid >> 5;          // cluster ranks share mt (consecutive bids)
    const int nt = bid & 31;
    const int m0 = mt * MT;
    const int n0 = nt * NT;
    const int w = tid >> 5;
    const int lane = tid & 31;
    const int g = lane >> 2;          // 0..7
    const int c = lane & 3;           // 0..3
    const int ss = w & 1;             // s-strip
    const int kg = w >> 1;            // k-group 0..3 (256-k slice)
    const int gtid = bid * NTHREADS + tid;

    uint32_t rank;
    asm("mov.u32 %0, %%cluster_ctarank;" : "=r"(rank));

    const uint32_t smb = (uint32_t)__cvta_generic_to_shared(sm);
    const uint32_t mbarA = smb + MBAR_W * 4;
    const uint32_t mbarB = mbarA + 8;
    const uint32_t mbarU = mbarA + 16;

    const unsigned base = *((volatile unsigned*)&g_release);

    if (tid == 0) {
        asm volatile("mbarrier.init.shared.b64 [%0], %1;" :: "r"(mbarA), "r"(1) : "memory");
        asm volatile("mbarrier.init.shared.b64 [%0], %1;" :: "r"(mbarB), "r"(1) : "memory");
        asm volatile("mbarrier.init.shared.b64 [%0], %1;" :: "r"(mbarU), "r"(1) : "memory");
    }
    __syncthreads();
    asm volatile("barrier.cluster.arrive.aligned;" ::: "memory");
    asm volatile("barrier.cluster.wait.aligned;" ::: "memory");

    // ---- init: u -> fp16 ubuf (smem-layout mirror) ----
    for (int j = gtid; j < HH * BSZ * (AD / 4); j += NCTA * NTHREADS) {
        int a4 = j & 31;              // 4-float chunk within ad
        int b = (j >> 5) & 127;
        int t = j >> 12;
        float4 v = *(const float4*)(u + ((size_t)b * HH + t) * AD + a4 * 4);
        int umt = b >> 5, bl = b & 31;
        int k2 = a4 * 2;              // first half2 index
        int o16u = k2 >> 3, c2 = k2 & 7;
        size_t idx = ((size_t)t * 4 + umt) * 2048
                   + (size_t)o16u * 128 + (size_t)bl * 4 + (c2 & 3)
                   + ((c2 & 4) ? UHI : 0);
        uint2 o2 = make_uint2(pack2(v.x, v.y), pack2(v.z, v.w));
        *(uint2*)(g_ubuf + idx) = o2;
    }
    // ---- init: xbuf[0] = fp16(x0) in mirrored layout; out[:,0,:] = x0 ----
    for (int j = gtid; j < BSZ * (SDIM / 4); j += NCTA * NTHREADS) {
        int s4c = j & 255;            // 4-float chunk within s
        int b = j >> 8;
        float4 v = ((const float4*)x0)[j];
        ((float4*)out)[(size_t)b * OUT_T * (SDIM / 4) + s4c] = v;
        int xmt = b >> 5, bl = b & 31;
        int k2 = s4c * 2;
        int o16 = k2 >> 3, c2 = k2 & 7;
        size_t idx = (size_t)xmt * XWORDS
                   + (size_t)o16 * 128 + (size_t)bl * 4 + (c2 & 3)
                   + ((c2 & 4) ? XHI : 0);
        uint2 o2 = make_uint2(pack2(v.x, v.y), pack2(v.z, v.w));
        *(uint2*)(g_xbuf[0] + idx) = o2;
    }

    // ---- fp16 weights into registers (invariant across all 512 steps) ----
    // x: 16 k16-groups (k = kg*256 + i*16); u: 2 k16-groups (k_u = kg*32 + jq*16)
    uint32_t ax[16][4];
    uint32_t au[2][4];
    {
        const int srow = n0 + ss * 16 + g;
#pragma unroll
        for (int i = 0; i < 16; i++) {
            int kb = kg * 256 + i * 16 + 2 * c;
            const float* r0 = A + (size_t)srow * SDIM;
            const float* r8 = A + (size_t)(srow + 8) * SDIM;
            ax[i][0] = pack2(r0[kb],     r0[kb + 1]);
            ax[i][1] = pack2(r8[kb],     r8[kb + 1]);
            ax[i][2] = pack2(r0[kb + 8], r0[kb + 9]);
            ax[i][3] = pack2(r8[kb + 8], r8[kb + 9]);
        }
#pragma unroll
        for (int jq = 0; jq < 2; jq++) {
            int kb = kg * 32 + jq * 16 + 2 * c;
            const float* r0 = Bm + (size_t)srow * AD;
            const float* r8 = Bm + (size_t)(srow + 8) * AD;
            au[jq][0] = pack2(r0[kb],     r0[kb + 1]);
            au[jq][1] = pack2(r8[kb],     r8[kb + 1]);
            au[jq][2] = pack2(r0[kb + 8], r0[kb + 9]);
            au[jq][3] = pack2(r8[kb + 8], r8[kb + 9]);
        }
    }

    grid_barrier(base + 1, bid, tid);   // init fence (global, once)

    for (int t = 0; t < HH; t++) {
        // ---- stage (v6 pattern): tid0 posts expects + issues multicast DMA ----
        if (tid == 0) {
            mbar_expect(mbarA, 32768);   // rank 0 + rank 2 slices (k 0..511)
            mbar_expect(mbarB, 32768);   // rank 1 + rank 3 slices (k 512..1023)
            mbar_expect(mbarU, 8192);
            const uint32_t* xsrc = g_xbuf[t & 1] + (size_t)mt * XWORDS
                                 + (size_t)rank * 4096;
            bulk_mc(smb + rank * 16384u, xsrc, 16384,
                    ((rank & 1) == 0) ? mbarA : mbarB, 0xF);
            if (rank == 3) {
                bulk_mc(smb + UO * 4u,
                        g_ubuf + ((size_t)t * 4 + mt) * 2048, 8192, mbarU, 0xF);
            }
        }

        // ---- MMA: warp kg (k slice 256) waits on its half ----
        float d[4][4];
#pragma unroll
        for (int nn = 0; nn < 4; nn++)
#pragma unroll
            for (int q = 0; q < 4; q++) d[nn][q] = 0.0f;

        mbar_wait((kg >= 2) ? mbarB : mbarA, (uint32_t)(t & 1));
        {
            const uint32_t* xs = sm + kg * 2048 + g * 4 + c;
#pragma unroll
            for (int i = 0; i < 16; i++) {
#pragma unroll
                for (int nn = 0; nn < 4; nn++) {
                    uint32_t b0 = xs[i * 128 + nn * 32];
                    uint32_t b1 = xs[i * 128 + nn * 32 + XHI];
                    mma_f16(d[nn], ax[i][0], ax[i][1], ax[i][2], ax[i][3], b0, b1);
                }
            }
        }
        mbar_wait(mbarU, (uint32_t)(t & 1));
        {
            const uint32_t* us = sm + UO + kg * 2 * 128 + g * 4 + c;
#pragma unroll
            for (int jq = 0; jq < 2; jq++) {
#pragma unroll
                for (int nn = 0; nn < 4; nn++) {
                    uint32_t b0 = us[jq * 128 + nn * 32];
                    uint32_t b1 = us[jq * 128 + nn * 32 + UHI];
                    mma_f16(d[nn], au[jq][0], au[jq][1], au[jq][2], au[jq][3], b0, b1);
                }
            }
        }

        // ---- partials to smem (v6 layout) ----
        {
            int rb = w * (16 * RED_STRIDE) + g * RED_STRIDE + 2 * c;
#pragma unroll
            for (int nn = 0; nn < 4; nn++) {
                *(float2*)(red + rb + nn * 8) = make_float2(d[nn][0], d[nn][1]);
                *(float2*)(red + rb + 8 * RED_STRIDE + nn * 8) = make_float2(d[nn][2], d[nn][3]);
            }
        }
        __syncthreads();

        // ---- reduce 4 k-partials; write fp32 out + fp16 xbuf ----
        {
            int b = tid >> 3;
            int s4 = (tid & 7) * 4;
            int ssr = s4 >> 4;
            float acc0 = 0.f, acc1 = 0.f, acc2 = 0.f, acc3 = 0.f;
#pragma unroll
            for (int kk = 0; kk < 4; kk++) {
                int wb = (kk * 2 + ssr) * (16 * RED_STRIDE) + b;
                acc0 += red[wb + ((s4 + 0) & 15) * RED_STRIDE];
                acc1 += red[wb + ((s4 + 1) & 15) * RED_STRIDE];
                acc2 += red[wb + ((s4 + 2) & 15) * RED_STRIDE];
                acc3 += red[wb + ((s4 + 3) & 15) * RED_STRIDE];
            }
            float* op = out + ((size_t)(m0 + b) * OUT_T + (t + 1)) * SDIM + n0 + s4;
            *(float4*)op = make_float4(acc0, acc1, acc2, acc3);

            int k2 = (n0 + s4) >> 1;
            int o16 = k2 >> 3, c2 = k2 & 7;
            size_t idx = (size_t)mt * XWORDS
                       + (size_t)o16 * 128 + (size_t)b * 4 + (c2 & 3)
                       + ((c2 & 4) ? XHI : 0);
            uint32_t* xp = g_xbuf[(t + 1) & 1] + idx;
            uint32_t w0 = pack2(acc0, acc1);
            uint32_t w1 = pack2(acc2, acc3);
            asm volatile("st.global.cg.v2.b32 [%0], {%1,%2};"
                         :: "l"(xp), "r"(w0), "r"(w1) : "memory");
        }

        // ---- 32-CTA group barrier (v6 verbatim) ----
        group_barrier(base + 2 + t, mt, nt, tid);
    }

    // Bump the epoch stream past all flag epochs for the next graph replay.
    if (bid == 0 && tid == 0) {
        __threadfence();
        *((volatile unsigned*)&g_release) = base + HH + 2;
    }
}

extern "C" void kernel_launch(void* const* d_in, const int* in_sizes, int n_in,
                              void* d_out, int out_size)
{
    const float* x0 = (const float*)d_in[0];
    const float* u  = (const float*)d_in[1];
    const float* A  = (const float*)d_in[2];
    const float* Bm = (const float*)d_in[3];
    float* out = (float*)d_out;

    cudaFuncSetAttribute(ssm_v10_kernel,
                         cudaFuncAttributeMaxDynamicSharedMemorySize, SMEM_BYTES);

    ssm_v10_kernel<<<NCTA, NTHREADS, SMEM_BYTES>>>(x0, u, A, Bm, out);
}

// round 12
// speedup vs baseline: 2.9438x; 1.3820x over previous
#include <cuda_runtime.h>
#include <cuda_fp16.h>
#include <cstdint>

// Problem constants
#define BSZ 128
#define SDIM 1024
#define AD 128
#define HH 512
#define NR (HH / 2)           // 256 rounds, 2 steps each
#define OUT_T 513

// Grid/tiling
#define NCTA 128
#define NTHREADS 256
#define CLUSTER 4
#define MT 32
#define NT 32

// SMEM word layout (uint32 = half2), same x scheme as v10:
//   x word(k2,b): o16=k2>>3, c2=k2&7 -> o16*128 + b*4 + (c2&3) + ((c2&4)?XHI:0)
// u region holds u_t (half 0) and u_{t+1} (half 1), 2048 words each.
#define XWORDS 16384
#define XHI 8192
#define UO 16384
#define UHI 1024
#define REDO 20480
#define RS 40
#define GMS (16 * RS)          // per-gemm slab per warp (640 words)
#define WS (2 * GMS)           // per-warp slab (1280 words)
#define MBAR_WOFF (REDO + 8 * WS)   // 30720
#define SMEM_BYTES (MBAR_WOFF * 4 + 48)

// Global sync state (zero-init once; epochs monotonic across graph replays)
__device__ unsigned g_arrive[NCTA];
__device__ unsigned g_release;
__device__ __align__(128) unsigned g_flag[4][32][32];

// fp16 state double buffer (v10 layout: rank slice r = words [r*4096,+4096))
__device__ __align__(16) uint32_t g_xbuf[2][4 * 16384];
// fp16 drive, PAIRED: [round][mt][u_t 2048 | u_{t+1} 2048]
__device__ __align__(16) uint32_t g_ubuf[(size_t)NR * 4 * 4096];
// A^T / B^T in x-layout ("columns as batch"), per 32-col block
__device__ __align__(16) uint32_t g_colA[32 * 16384];
__device__ __align__(16) uint32_t g_colB[4 * 16384];
// Precomputed A^2 [1024x1024] and A*B [1024x128], fp32
__device__ float g_a2[SDIM * SDIM];
__device__ float g_ab[SDIM * AD];

__device__ __forceinline__ void grid_barrier(unsigned epoch, int bid, int tid)
{
    __syncthreads();
    if (tid == 0) {
        __threadfence();
        *((volatile unsigned*)&g_arrive[bid]) = epoch;
    }
    if (bid == 0) {
        if (tid < NCTA) {
            while ((int)(*((volatile unsigned*)&g_arrive[tid]) - epoch) < 0) { }
        }
        __syncthreads();
        if (tid == 0) {
            __threadfence();
            *((volatile unsigned*)&g_release) = epoch;
        }
    } else if (tid == 0) {
        while ((int)(*((volatile unsigned*)&g_release) - epoch) < 0) { }
    }
    __syncthreads();
    __threadfence();
}

// 32-CTA group flag barrier (v10 verbatim; the 1752us structure)
__device__ __forceinline__ void group_barrier(unsigned epoch, int mt_, int nt_, int tid)
{
    __threadfence();
    __syncthreads();
    if (tid == 0) {
        *((volatile unsigned*)&g_flag[mt_][nt_][0]) = epoch;
    }
    if (tid < 32) {
        while ((int)(*((volatile unsigned*)&g_flag[mt_][tid][0]) - epoch) < 0) { }
    }
    __syncthreads();
}

__device__ __forceinline__ uint32_t pack2(float x, float y)
{
    __half2 h = __floats2half2_rn(x, y);
    return *(uint32_t*)&h;
}

__device__ __forceinline__ void mma_f16(float* d,
                                        uint32_t a0, uint32_t a1, uint32_t a2, uint32_t a3,
                                        uint32_t b0, uint32_t b1)
{
    asm volatile("mma.sync.aligned.m16n8k16.row.col.f32.f16.f16.f32 "
                 "{%0,%1,%2,%3}, {%4,%5,%6,%7}, {%8,%9}, {%0,%1,%2,%3};"
                 : "+f"(d[0]), "+f"(d[1]), "+f"(d[2]), "+f"(d[3])
                 : "r"(a0), "r"(a1), "r"(a2), "r"(a3), "r"(b0), "r"(b1));
}

__device__ __forceinline__ void bulk_mc(uint32_t dst_smem, const void* src,
                                        uint32_t bytes, uint32_t mbar, uint16_t mask)
{
    asm volatile("cp.async.bulk.shared::cluster.global.mbarrier::complete_tx::bytes"
                 ".multicast::cluster [%0], [%1], %2, [%3], %4;"
                 :: "r"(dst_smem), "l"(src), "r"(bytes), "r"(mbar), "h"(mask)
                 : "memory");
}

__device__ __forceinline__ void bulk_cp(uint32_t dst_smem, const void* src,
                                        uint32_t bytes, uint32_t mbar)
{
    asm volatile("cp.async.bulk.shared::cluster.global.mbarrier::complete_tx::bytes"
                 " [%0], [%1], %2, [%3];"
                 :: "r"(dst_smem), "l"(src), "r"(bytes), "r"(mbar)
                 : "memory");
}

__device__ __forceinline__ void mbar_expect(uint32_t mbar, uint32_t bytes)
{
    asm volatile("mbarrier.arrive.expect_tx.shared.b64 _, [%0], %1;"
                 :: "r"(mbar), "r"(bytes) : "memory");
}

__device__ __forceinline__ void mbar_wait(uint32_t mbar, uint32_t parity)
{
    uint32_t done;
    asm volatile("{\n\t.reg .pred p;\n\t"
                 "mbarrier.try_wait.parity.acquire.cta.shared::cta.b64 p, [%1], %2;\n\t"
                 "selp.b32 %0, 1, 0, p;\n\t}"
                 : "=r"(done) : "r"(mbar), "r"(parity) : "memory");
    if (!done) {
        asm volatile("{\n\t.reg .pred P1;\n\t"
                     "W%=:\n\t"
                     "mbarrier.try_wait.parity.acquire.cta.shared::cta.b64 P1, [%0], %1, 0x989680;\n\t"
                     "@P1 bra.uni D%=;\n\t"
                     "bra.uni W%=;\n\t"
                     "D%=:\n\t}"
                     :: "r"(mbar), "r"(parity) : "memory");
    }
}

extern "C" __global__ void __launch_bounds__(NTHREADS, 1) __cluster_dims__(CLUSTER, 1, 1)
ssm_v11_kernel(const float* __restrict__ x0, const float* __restrict__ u,
               const float* __restrict__ A, const float* __restrict__ Bm,
               float* __restrict__ out)
{
    extern __shared__ uint32_t sm[];
    float* red = (float*)(sm + REDO);

    const int tid = threadIdx.x;
    const int bid = blockIdx.x;
    const int mt = bid >> 5;
    const int nt = bid & 31;
    const int m0 = mt * MT;
    const int n0 = nt * NT;
    const int w = tid >> 5;
    const int lane = tid & 31;
    const int g = lane >> 2;
    const int c = lane & 3;
    const int ss = w & 1;             // s-strip
    const int kg = w >> 1;            // k-quarter 0..3
    const int gtid = bid * NTHREADS + tid;

    uint32_t rank;
    asm("mov.u32 %0, %%cluster_ctarank;" : "=r"(rank));

    const uint32_t smb = (uint32_t)__cvta_generic_to_shared(sm);
    const uint32_t mbarA = smb + MBAR_WOFF * 4;
    const uint32_t mbarB = mbarA + 8;
    const uint32_t mbarU = mbarA + 16;
    const uint32_t mbarP = mbarA + 24;

    const unsigned base = *((volatile unsigned*)&g_release);

    if (tid == 0) {
        asm volatile("mbarrier.init.shared.b64 [%0], %1;" :: "r"(mbarA), "r"(1) : "memory");
        asm volatile("mbarrier.init.shared.b64 [%0], %1;" :: "r"(mbarB), "r"(1) : "memory");
        asm volatile("mbarrier.init.shared.b64 [%0], %1;" :: "r"(mbarU), "r"(1) : "memory");
        asm volatile("mbarrier.init.shared.b64 [%0], %1;" :: "r"(mbarP), "r"(1) : "memory");
    }
    __syncthreads();
    asm volatile("barrier.cluster.arrive.aligned;" ::: "memory");
    asm volatile("barrier.cluster.wait.aligned;" ::: "memory");

    // ---- init: u -> fp16 ubuf, PAIRED per round ----
    for (int j = gtid; j < HH * BSZ * (AD / 4); j += NCTA * NTHREADS) {
        int a4 = j & 31;
        int b = (j >> 5) & 127;
        int t = j >> 12;
        float4 v = *(const float4*)(u + ((size_t)b * HH + t) * AD + a4 * 4);
        int umt = b >> 5, bl = b & 31;
        int k2 = a4 * 2, o16u = k2 >> 3, c2 = k2 & 7;
        size_t idx = ((size_t)(t >> 1) * 4 + umt) * 4096 + (size_t)(t & 1) * 2048
                   + (size_t)o16u * 128 + (size_t)bl * 4 + (c2 & 3)
                   + ((c2 & 4) ? UHI : 0);
        *(uint2*)(g_ubuf + idx) = make_uint2(pack2(v.x, v.y), pack2(v.z, v.w));
    }
    // ---- init: xbuf[0] = fp16(x0); out[:,0,:] = x0 ----
    for (int j = gtid; j < BSZ * (SDIM / 4); j += NCTA * NTHREADS) {
        int s4c = j & 255;
        int b = j >> 8;
        float4 v = ((const float4*)x0)[j];
        ((float4*)out)[(size_t)b * OUT_T * (SDIM / 4) + s4c] = v;
        int xmt = b >> 5, bl = b & 31;
        int k2 = s4c * 2, o16 = k2 >> 3, c2 = k2 & 7;
        size_t idx = (size_t)xmt * XWORDS + (size_t)o16 * 128 + (size_t)bl * 4
                   + (c2 & 3) + ((c2 & 4) ? XHI : 0);
        *(uint2*)(g_xbuf[0] + idx) = make_uint2(pack2(v.x, v.y), pack2(v.z, v.w));
    }
    // ---- init: colA = A^T in x-layout (pairs along j), per 32-col block ----
    for (int j = gtid; j < 512 * 1024; j += NCTA * NTHREADS) {
        int k = j & 1023, j2 = j >> 10;
        float v0 = A[(size_t)(2 * j2) * SDIM + k];
        float v1 = A[(size_t)(2 * j2 + 1) * SDIM + k];
        int kb = k >> 5, kcol = k & 31, o16 = j2 >> 3, c2 = j2 & 7;
        g_colA[(size_t)kb * 16384 + o16 * 128 + kcol * 4 + (c2 & 3)
               + ((c2 & 4) ? 8192 : 0)] = pack2(v0, v1);
    }
    // ---- init: colB = B^T in x-layout ----
    for (int j = gtid; j < 512 * 128; j += NCTA * NTHREADS) {
        int ku = j & 127, j2 = j >> 7;
        float v0 = Bm[(size_t)(2 * j2) * AD + ku];
        float v1 = Bm[(size_t)(2 * j2 + 1) * AD + ku];
        int kb = ku >> 5, kcol = ku & 31, o16 = j2 >> 3, c2 = j2 & 7;
        g_colB[(size_t)kb * 16384 + o16 * 128 + kcol * 4 + (c2 & 3)
               + ((c2 & 4) ? 8192 : 0)] = pack2(v0, v1);
    }

    // ---- fp16 A and B weights into registers ----
    uint32_t axA[16][4], auB[2][4];
    const int srow = n0 + ss * 16 + g;
    {
#pragma unroll
        for (int i = 0; i < 16; i++) {
            int kb = kg * 256 + i * 16 + 2 * c;
            const float* r0 = A + (size_t)srow * SDIM;
            const float* r8 = A + (size_t)(srow + 8) * SDIM;
            axA[i][0] = pack2(r0[kb],     r0[kb + 1]);
            axA[i][1] = pack2(r8[kb],     r8[kb + 1]);
            axA[i][2] = pack2(r0[kb + 8], r0[kb + 9]);
            axA[i][3] = pack2(r8[kb + 8], r8[kb + 9]);
        }
#pragma unroll
        for (int jq = 0; jq < 2; jq++) {
            int kb = kg * 32 + jq * 16 + 2 * c;
            const float* r0 = Bm + (size_t)srow * AD;
            const float* r8 = Bm + (size_t)(srow + 8) * AD;
            auB[jq][0] = pack2(r0[kb],     r0[kb + 1]);
            auB[jq][1] = pack2(r8[kb],     r8[kb + 1]);
            auB[jq][2] = pack2(r0[kb + 8], r0[kb + 9]);
            auB[jq][3] = pack2(r8[kb + 8], r8[kb + 9]);
        }
    }

    grid_barrier(base + 1, bid, tid);   // conversions visible

    // ---- precompute A2 (8 blocks) + AB (1 block) with the MMA machinery ----
    for (int pr = 0; pr < 9; pr++) {
        if (tid == 0) {
            mbar_expect(mbarP, 65536);
            const uint32_t* src = (pr < 8)
                ? g_colA + (size_t)(mt * 8 + pr) * 16384
                : g_colB + (size_t)mt * 16384;
            bulk_cp(smb, src, 65536, mbarP);
        }
        float d[4][4];
#pragma unroll
        for (int nn = 0; nn < 4; nn++)
#pragma unroll
            for (int e = 0; e < 4; e++) d[nn][e] = 0.0f;

        mbar_wait(mbarP, (uint32_t)(pr & 1));
        {
            const uint32_t* xs = sm + kg * 2048 + g * 4 + c;
#pragma unroll
            for (int i = 0; i < 16; i++) {
#pragma unroll
                for (int nn = 0; nn < 4; nn++) {
                    uint32_t b0 = xs[i * 128 + nn * 32];
                    uint32_t b1 = xs[i * 128 + nn * 32 + XHI];
                    mma_f16(d[nn], axA[i][0], axA[i][1], axA[i][2], axA[i][3], b0, b1);
                }
            }
        }
        {
            int rb = w * WS + g * RS + 2 * c;
#pragma unroll
            for (int nn = 0; nn < 4; nn++) {
                *(float2*)(red + rb + nn * 8) = make_float2(d[nn][0], d[nn][1]);
                *(float2*)(red + rb + 8 * RS + nn * 8) = make_float2(d[nn][2], d[nn][3]);
            }
        }
        __syncthreads();
        {
            int b = tid >> 3;
            int s4 = (tid & 7) * 4;
            int ssr = s4 >> 4;
            float acc[4] = {0.f, 0.f, 0.f, 0.f};
#pragma unroll
            for (int kk = 0; kk < 4; kk++) {
                int wb = (kk * 2 + ssr) * WS + b;
#pragma unroll
                for (int i = 0; i < 4; i++)
                    acc[i] += red[wb + ((s4 + i) & 15) * RS];
            }
            if (pr < 8) {
                int kb = mt * 8 + pr;
#pragma unroll
                for (int i = 0; i < 4; i++)
                    g_a2[(size_t)(n0 + s4 + i) * SDIM + kb * 32 + b] = acc[i];
            } else {
#pragma unroll
                for (int i = 0; i < 4; i++)
                    g_ab[(size_t)(n0 + s4 + i) * AD + mt * 32 + b] = acc[i];
            }
        }
        __syncthreads();
    }

    grid_barrier(base + 2, bid, tid);   // A2/AB visible everywhere

    // ---- fp16 A2 and AB weights into registers ----
    uint32_t ax2[16][4], auAB[2][4];
    {
#pragma unroll
        for (int i = 0; i < 16; i++) {
            int kb = kg * 256 + i * 16 + 2 * c;
            const float* r0 = g_a2 + (size_t)srow * SDIM;
            const float* r8 = g_a2 + (size_t)(srow + 8) * SDIM;
            ax2[i][0] = pack2(r0[kb],     r0[kb + 1]);
            ax2[i][1] = pack2(r8[kb],     r8[kb + 1]);
            ax2[i][2] = pack2(r0[kb + 8], r0[kb + 9]);
            ax2[i][3] = pack2(r8[kb + 8], r8[kb + 9]);
        }
#pragma unroll
        for (int jq = 0; jq < 2; jq++) {
            int kb = kg * 32 + jq * 16 + 2 * c;
            const float* r0 = g_ab + (size_t)srow * AD;
            const float* r8 = g_ab + (size_t)(srow + 8) * AD;
            auAB[jq][0] = pack2(r0[kb],     r0[kb + 1]);
            auAB[jq][1] = pack2(r8[kb],     r8[kb + 1]);
            auAB[jq][2] = pack2(r0[kb + 8], r0[kb + 9]);
            auAB[jq][3] = pack2(r8[kb + 8], r8[kb + 9]);
        }
    }

    // ---- main loop: 256 rounds, 2 steps each ----
    for (int r = 0; r < NR; r++) {
        if (tid == 0) {
            mbar_expect(mbarA, 32768);
            mbar_expect(mbarB, 32768);
            mbar_expect(mbarU, 16384);
            const uint32_t* xsrc = g_xbuf[r & 1] + (size_t)mt * XWORDS
                                 + (size_t)rank * 4096;
            bulk_mc(smb + rank * 16384u, xsrc, 16384,
                    ((rank & 1) == 0) ? mbarA : mbarB, 0xF);
            if (rank == 3) {
                bulk_mc(smb + UO * 4u,
                        g_ubuf + ((size_t)r * 4 + mt) * 4096, 16384, mbarU, 0xF);
            }
        }

        float d1[4][4], d2[4][4];
#pragma unroll
        for (int nn = 0; nn < 4; nn++)
#pragma unroll
            for (int e = 0; e < 4; e++) { d1[nn][e] = 0.0f; d2[nn][e] = 0.0f; }

        mbar_wait((kg >= 2) ? mbarB : mbarA, (uint32_t)(r & 1));
        {
            const uint32_t* xs = sm + kg * 2048 + g * 4 + c;
#pragma unroll
            for (int i = 0; i < 16; i++) {
#pragma unroll
                for (int nn = 0; nn < 4; nn++) {
                    uint32_t b0 = xs[i * 128 + nn * 32];
                    uint32_t b1 = xs[i * 128 + nn * 32 + XHI];
                    mma_f16(d1[nn], axA[i][0], axA[i][1], axA[i][2], axA[i][3], b0, b1);
                    mma_f16(d2[nn], ax2[i][0], ax2[i][1], ax2[i][2], ax2[i][3], b0, b1);
                }
            }
        }
        mbar_wait(mbarU, (uint32_t)(r & 1));
        {
            const uint32_t* us = sm + UO + kg * 2 * 128 + g * 4 + c;
#pragma unroll
            for (int jq = 0; jq < 2; jq++) {
#pragma unroll
                for (int nn = 0; nn < 4; nn++) {
                    uint32_t b0 = us[jq * 128 + nn * 32];
                    uint32_t b1 = us[jq * 128 + nn * 32 + UHI];
                    mma_f16(d1[nn], auB[jq][0], auB[jq][1], auB[jq][2], auB[jq][3], b0, b1);
                    mma_f16(d2[nn], auAB[jq][0], auAB[jq][1], auAB[jq][2], auAB[jq][3], b0, b1);
                }
            }
            const uint32_t* us2 = us + 2048;   // u_{t+1}, B weights reused
#pragma unroll
            for (int jq = 0; jq < 2; jq++) {
#pragma unroll
                for (int nn = 0; nn < 4; nn++) {
                    uint32_t b0 = us2[jq * 128 + nn * 32];
                    uint32_t b1 = us2[jq * 128 + nn * 32 + UHI];
                    mma_f16(d2[nn], auB[jq][0], auB[jq][1], auB[jq][2], auB[jq][3], b0, b1);
                }
            }
        }

        // ---- partials: [warp][gemm][16 rows][RS] ----
        {
            int rb = w * WS + g * RS + 2 * c;
#pragma unroll
            for (int nn = 0; nn < 4; nn++) {
                *(float2*)(red + rb + nn * 8) = make_float2(d1[nn][0], d1[nn][1]);
                *(float2*)(red + rb + 8 * RS + nn * 8) = make_float2(d1[nn][2], d1[nn][3]);
                *(float2*)(red + rb + GMS + nn * 8) = make_float2(d2[nn][0], d2[nn][1]);
                *(float2*)(red + rb + GMS + 8 * RS + nn * 8) = make_float2(d2[nn][2], d2[nn][3]);
            }
        }
        __syncthreads();

        // ---- reduce both gemms; write x_{2r+1}, x_{2r+2} ----
        {
            int b = tid >> 3;
            int s4 = (tid & 7) * 4;
            int ssr = s4 >> 4;
            float a1[4] = {0.f, 0.f, 0.f, 0.f};
            float a2v[4] = {0.f, 0.f, 0.f, 0.f};
#pragma unroll
            for (int kk = 0; kk < 4; kk++) {
                int wb = (kk * 2 + ssr) * WS + b;
#pragma unroll
                for (int i = 0; i < 4; i++) {
                    a1[i] += red[wb + ((s4 + i) & 15) * RS];
                    a2v[i] += red[wb + GMS + ((s4 + i) & 15) * RS];
                }
            }
            float* op1 = out + ((size_t)(m0 + b) * OUT_T + (2 * r + 1)) * SDIM + n0 + s4;
            *(float4*)op1 = make_float4(a1[0], a1[1], a1[2], a1[3]);
            float* op2 = out + ((size_t)(m0 + b) * OUT_T + (2 * r + 2)) * SDIM + n0 + s4;
            *(float4*)op2 = make_float4(a2v[0], a2v[1], a2v[2], a2v[3]);

            int k2 = (n0 + s4) >> 1;
            int o16 = k2 >> 3, c2 = k2 & 7;
            size_t idx = (size_t)mt * XWORDS + (size_t)o16 * 128 + (size_t)b * 4
                       + (c2 & 3) + ((c2 & 4) ? XHI : 0);
            uint32_t* xp = g_xbuf[(r + 1) & 1] + idx;
            uint32_t w0 = pack2(a2v[0], a2v[1]);
            uint32_t w1 = pack2(a2v[2], a2v[3]);
            asm volatile("st.global.cg.v2.b32 [%0], {%1,%2};"
                         :: "l"(xp), "r"(w0), "r"(w1) : "memory");
        }

        group_barrier(base + 3 + r, mt, nt, tid);
    }

    // Bump epoch stream for the next graph replay.
    if (bid == 0 && tid == 0) {
        __threadfence();
        *((volatile unsigned*)&g_release) = base + 3 + NR;
    }
}

extern "C" void kernel_launch(void* const* d_in, const int* in_sizes, int n_in,
                              void* d_out, int out_size)
{
    const float* x0 = (const float*)d_in[0];
    const float* u  = (const float*)d_in[1];
    const float* A  = (const float*)d_in[2];
    const float* Bm = (const float*)d_in[3];
    float* out = (float*)d_out;

    cudaFuncSetAttribute(ssm_v11_kernel,
                         cudaFuncAttributeMaxDynamicSharedMemorySize, SMEM_BYTES);

    ssm_v11_kernel<<<NCTA, NTHREADS, SMEM_BYTES>>>(x0, u, A, Bm, out);
}

// round 13
// speedup vs baseline: 2.9607x; 1.0057x over previous
#include <cuda_runtime.h>
#include <cuda_fp16.h>
#include <cstdint>

// Problem constants
#define BSZ 128
#define SDIM 1024
#define AD 128
#define HH 512
#define NR (HH / 2)           // 256 rounds, 2 steps each
#define OUT_T 513

// Grid/tiling
#define NCTA 128
#define NTHREADS 256
#define CLUSTER 4
#define MT 32
#define NT 32

// SMEM word layout (uint32 = half2).
// x buffers: XBUF(s) = s*16384, internal layout as v10/v11:
//   word(k2,b): o16=k2>>3, c2=k2&7 -> o16*128 + b*4 + (c2&3) + ((c2&4)?XHI:0)
// u buffers: UO + s*4096 (each: u_t 2048 | u_{t+1} 2048; UHI within each block)
#define XWORDS 16384
#define XHI 8192
#define UO 32768
#define UHI 1024
#define REDO 40960
#define RS 40
#define GMS (16 * RS)          // 640 words per warp per slab
#define RED1 (REDO + 8 * GMS)  // 46080: slab1 (deferred gemm1)
#define MBAR_WOFF (RED1 + 8 * GMS)  // 51200
#define SMEM_BYTES (MBAR_WOFF * 4 + 64)

// Global sync state (zero-init once; epochs monotonic across graph replays)
__device__ unsigned g_arrive[NCTA];
__device__ unsigned g_release;
__device__ __align__(128) unsigned g_flag[4][32][32];

// fp16 state double buffer (rank slice r = words [r*4096,+4096))
__device__ __align__(16) uint32_t g_xbuf[2][4 * 16384];
// fp16 drive, PAIRED: [round][mt][u_t 2048 | u_{t+1} 2048]
__device__ __align__(16) uint32_t g_ubuf[(size_t)NR * 4 * 4096];
// A^T / B^T in x-layout ("columns as batch"), per 32-col block
__device__ __align__(16) uint32_t g_colA[32 * 16384];
__device__ __align__(16) uint32_t g_colB[4 * 16384];
// Precomputed A^2 [1024x1024] and A*B [1024x128], fp32
__device__ float g_a2[SDIM * SDIM];
__device__ float g_ab[SDIM * AD];

__device__ __forceinline__ void grid_barrier(unsigned epoch, int bid, int tid)
{
    __syncthreads();
    if (tid == 0) {
        __threadfence();
        *((volatile unsigned*)&g_arrive[bid]) = epoch;
    }
    if (bid == 0) {
        if (tid < NCTA) {
            while ((int)(*((volatile unsigned*)&g_arrive[tid]) - epoch) < 0) { }
        }
        __syncthreads();
        if (tid == 0) {
            __threadfence();
            *((volatile unsigned*)&g_release) = epoch;
        }
    } else if (tid == 0) {
        while ((int)(*((volatile unsigned*)&g_release) - epoch) < 0) { }
    }
    __syncthreads();
    __threadfence();
}

__device__ __forceinline__ uint32_t pack2(float x, float y)
{
    __half2 h = __floats2half2_rn(x, y);
    return *(uint32_t*)&h;
}

__device__ __forceinline__ void mma_f16(float* d,
                                        uint32_t a0, uint32_t a1, uint32_t a2, uint32_t a3,
                                        uint32_t b0, uint32_t b1)
{
    asm volatile("mma.sync.aligned.m16n8k16.row.col.f32.f16.f16.f32 "
                 "{%0,%1,%2,%3}, {%4,%5,%6,%7}, {%8,%9}, {%0,%1,%2,%3};"
                 : "+f"(d[0]), "+f"(d[1]), "+f"(d[2]), "+f"(d[3])
                 : "r"(a0), "r"(a1), "r"(a2), "r"(a3), "r"(b0), "r"(b1));
}

__device__ __forceinline__ void bulk_mc(uint32_t dst_smem, const void* src,
                                        uint32_t bytes, uint32_t mbar, uint16_t mask)
{
    asm volatile("cp.async.bulk.shared::cluster.global.mbarrier::complete_tx::bytes"
                 ".multicast::cluster [%0], [%1], %2, [%3], %4;"
                 :: "r"(dst_smem), "l"(src), "r"(bytes), "r"(mbar), "h"(mask)
                 : "memory");
}

__device__ __forceinline__ void bulk_cp(uint32_t dst_smem, const void* src,
                                        uint32_t bytes, uint32_t mbar)
{
    asm volatile("cp.async.bulk.shared::cluster.global.mbarrier::complete_tx::bytes"
                 " [%0], [%1], %2, [%3];"
                 :: "r"(dst_smem), "l"(src), "r"(bytes), "r"(mbar)
                 : "memory");
}

__device__ __forceinline__ void mbar_expect(uint32_t mbar, uint32_t bytes)
{
    asm volatile("mbarrier.arrive.expect_tx.shared.b64 _, [%0], %1;"
                 :: "r"(mbar), "r"(bytes) : "memory");
}

__device__ __forceinline__ void mbar_wait(uint32_t mbar, uint32_t parity)
{
    uint32_t done;
    asm volatile("{\n\t.reg .pred p;\n\t"
                 "mbarrier.try_wait.parity.acquire.cta.shared::cta.b64 p, [%1], %2;\n\t"
                 "selp.b32 %0, 1, 0, p;\n\t}"
                 : "=r"(done) : "r"(mbar), "r"(parity) : "memory");
    if (!done) {
        asm volatile("{\n\t.reg .pred P1;\n\t"
                     "W%=:\n\t"
                     "mbarrier.try_wait.parity.acquire.cta.shared::cta.b64 P1, [%0], %1, 0x989680;\n\t"
                     "@P1 bra.uni D%=;\n\t"
                     "bra.uni W%=;\n\t"
                     "D%=:\n\t}"
                     :: "r"(mbar), "r"(parity) : "memory");
    }
}

extern "C" __global__ void __launch_bounds__(NTHREADS, 1) __cluster_dims__(CLUSTER, 1, 1)
ssm_v12_kernel(const float* __restrict__ x0, const float* __restrict__ u,
               const float* __restrict__ A, const float* __restrict__ Bm,
               float* __restrict__ out)
{
    extern __shared__ uint32_t sm[];
    float* red2 = (float*)(sm + REDO);
    float* red1 = (float*)(sm + RED1);

    const int tid = threadIdx.x;
    const int bid = blockIdx.x;
    const int mt = bid >> 5;
    const int nt = bid & 31;
    const int m0 = mt * MT;
    const int n0 = nt * NT;
    const int w = tid >> 5;
    const int lane = tid & 31;
    const int g = lane >> 2;
    const int c = lane & 3;
    const int ss = w & 1;
    const int kg = w >> 1;
    const int gtid = bid * NTHREADS + tid;

    uint32_t rank;
    asm("mov.u32 %0, %%cluster_ctarank;" : "=r"(rank));

    const uint32_t smb = (uint32_t)__cvta_generic_to_shared(sm);
    const uint32_t mbarA = smb + MBAR_WOFF * 4;
    const uint32_t mbarB = mbarA + 8;
    const uint32_t mbarUb = mbarA + 16;   // mbarU[s] = mbarUb + s*8
    const uint32_t mbarP = mbarA + 32;

    const unsigned base = *((volatile unsigned*)&g_release);

    if (tid == 0) {
        asm volatile("mbarrier.init.shared.b64 [%0], %1;" :: "r"(mbarA), "r"(1) : "memory");
        asm volatile("mbarrier.init.shared.b64 [%0], %1;" :: "r"(mbarB), "r"(1) : "memory");
        asm volatile("mbarrier.init.shared.b64 [%0], %1;" :: "r"(mbarUb), "r"(1) : "memory");
        asm volatile("mbarrier.init.shared.b64 [%0], %1;" :: "r"(mbarUb + 8), "r"(1) : "memory");
        asm volatile("mbarrier.init.shared.b64 [%0], %1;" :: "r"(mbarP), "r"(1) : "memory");
    }
    __syncthreads();
    asm volatile("barrier.cluster.arrive.aligned;" ::: "memory");
    asm volatile("barrier.cluster.wait.aligned;" ::: "memory");

    // ---- init: u -> fp16 ubuf, PAIRED per round ----
    for (int j = gtid; j < HH * BSZ * (AD / 4); j += NCTA * NTHREADS) {
        int a4 = j & 31;
        int b = (j >> 5) & 127;
        int t = j >> 12;
        float4 v = *(const float4*)(u + ((size_t)b * HH + t) * AD + a4 * 4);
        int umt = b >> 5, bl = b & 31;
        int k2 = a4 * 2, o16u = k2 >> 3, c2 = k2 & 7;
        size_t idx = ((size_t)(t >> 1) * 4 + umt) * 4096 + (size_t)(t & 1) * 2048
                   + (size_t)o16u * 128 + (size_t)bl * 4 + (c2 & 3)
                   + ((c2 & 4) ? UHI : 0);
        *(uint2*)(g_ubuf + idx) = make_uint2(pack2(v.x, v.y), pack2(v.z, v.w));
    }
    // ---- init: xbuf[0] = fp16(x0); out[:,0,:] = x0 ----
    for (int j = gtid; j < BSZ * (SDIM / 4); j += NCTA * NTHREADS) {
        int s4c = j & 255;
        int b = j >> 8;
        float4 v = ((const float4*)x0)[j];
        ((float4*)out)[(size_t)b * OUT_T * (SDIM / 4) + s4c] = v;
        int xmt = b >> 5, bl = b & 31;
        int k2 = s4c * 2, o16 = k2 >> 3, c2 = k2 & 7;
        size_t idx = (size_t)xmt * XWORDS + (size_t)o16 * 128 + (size_t)bl * 4
                   + (c2 & 3) + ((c2 & 4) ? XHI : 0);
        *(uint2*)(g_xbuf[0] + idx) = make_uint2(pack2(v.x, v.y), pack2(v.z, v.w));
    }
    // ---- init: colA = A^T in x-layout; colB = B^T in x-layout ----
    for (int j = gtid; j < 512 * 1024; j += NCTA * NTHREADS) {
        int k = j & 1023, j2 = j >> 10;
        float v0 = A[(size_t)(2 * j2) * SDIM + k];
        float v1 = A[(size_t)(2 * j2 + 1) * SDIM + k];
        int kb = k >> 5, kcol = k & 31, o16 = j2 >> 3, c2 = j2 & 7;
        g_colA[(size_t)kb * 16384 + o16 * 128 + kcol * 4 + (c2 & 3)
               + ((c2 & 4) ? 8192 : 0)] = pack2(v0, v1);
    }
    for (int j = gtid; j < 512 * 128; j += NCTA * NTHREADS) {
        int ku = j & 127, j2 = j >> 7;
        float v0 = Bm[(size_t)(2 * j2) * AD + ku];
        float v1 = Bm[(size_t)(2 * j2 + 1) * AD + ku];
        int kb = ku >> 5, kcol = ku & 31, o16 = j2 >> 3, c2 = j2 & 7;
        g_colB[(size_t)kb * 16384 + o16 * 128 + kcol * 4 + (c2 & 3)
               + ((c2 & 4) ? 8192 : 0)] = pack2(v0, v1);
    }

    // ---- fp16 A and B weights into registers ----
    uint32_t axA[16][4], auB[2][4];
    const int srow = n0 + ss * 16 + g;
    {
#pragma unroll
        for (int i = 0; i < 16; i++) {
            int kb = kg * 256 + i * 16 + 2 * c;
            const float* r0 = A + (size_t)srow * SDIM;
            const float* r8 = A + (size_t)(srow + 8) * SDIM;
            axA[i][0] = pack2(r0[kb],     r0[kb + 1]);
            axA[i][1] = pack2(r8[kb],     r8[kb + 1]);
            axA[i][2] = pack2(r0[kb + 8], r0[kb + 9]);
            axA[i][3] = pack2(r8[kb + 8], r8[kb + 9]);
        }
#pragma unroll
        for (int jq = 0; jq < 2; jq++) {
            int kb = kg * 32 + jq * 16 + 2 * c;
            const float* r0 = Bm + (size_t)srow * AD;
            const float* r8 = Bm + (size_t)(srow + 8) * AD;
            auB[jq][0] = pack2(r0[kb],     r0[kb + 1]);
            auB[jq][1] = pack2(r8[kb],     r8[kb + 1]);
            auB[jq][2] = pack2(r0[kb + 8], r0[kb + 9]);
            auB[jq][3] = pack2(r8[kb + 8], r8[kb + 9]);
        }
    }

    grid_barrier(base + 1, bid, tid);

    // ---- precompute A2 (8 blocks) + AB (1 block) ----
    for (int pr = 0; pr < 9; pr++) {
        if (tid == 0) {
            mbar_expect(mbarP, 65536);
            const uint32_t* src = (pr < 8)
                ? g_colA + (size_t)(mt * 8 + pr) * 16384
                : g_colB + (size_t)mt * 16384;
            bulk_cp(smb, src, 65536, mbarP);
        }
        float d[4][4];
#pragma unroll
        for (int nn = 0; nn < 4; nn++)
#pragma unroll
            for (int e = 0; e < 4; e++) d[nn][e] = 0.0f;

        mbar_wait(mbarP, (uint32_t)(pr & 1));
        {
            const uint32_t* xs = sm + kg * 2048 + g * 4 + c;
#pragma unroll
            for (int i = 0; i < 16; i++) {
#pragma unroll
                for (int nn = 0; nn < 4; nn++) {
                    uint32_t b0 = xs[i * 128 + nn * 32];
                    uint32_t b1 = xs[i * 128 + nn * 32 + XHI];
                    mma_f16(d[nn], axA[i][0], axA[i][1], axA[i][2], axA[i][3], b0, b1);
                }
            }
        }
        {
            int rb = w * GMS + g * RS + 2 * c;
#pragma unroll
            for (int nn = 0; nn < 4; nn++) {
                *(float2*)(red2 + rb + nn * 8) = make_float2(d[nn][0], d[nn][1]);
                *(float2*)(red2 + rb + 8 * RS + nn * 8) = make_float2(d[nn][2], d[nn][3]);
            }
        }
        __syncthreads();
        {
            int b = tid >> 3;
            int s4 = (tid & 7) * 4;
            int ssr = s4 >> 4;
            float acc[4] = {0.f, 0.f, 0.f, 0.f};
#pragma unroll
            for (int kk = 0; kk < 4; kk++) {
                int wb = (kk * 2 + ssr) * GMS + b;
#pragma unroll
                for (int i = 0; i < 4; i++)
                    acc[i] += red2[wb + ((s4 + i) & 15) * RS];
            }
            if (pr < 8) {
                int kb = mt * 8 + pr;
#pragma unroll
                for (int i = 0; i < 4; i++)
                    g_a2[(size_t)(n0 + s4 + i) * SDIM + kb * 32 + b] = acc[i];
            } else {
#pragma unroll
                for (int i = 0; i < 4; i++)
                    g_ab[(size_t)(n0 + s4 + i) * AD + mt * 32 + b] = acc[i];
            }
        }
        __syncthreads();
    }

    grid_barrier(base + 2, bid, tid);

    // ---- fp16 A2 and AB weights into registers ----
    uint32_t ax2[16][4], auAB[2][4];
    {
#pragma unroll
        for (int i = 0; i < 16; i++) {
            int kb = kg * 256 + i * 16 + 2 * c;
            const float* r0 = g_a2 + (size_t)srow * SDIM;
            const float* r8 = g_a2 + (size_t)(srow + 8) * SDIM;
            ax2[i][0] = pack2(r0[kb],     r0[kb + 1]);
            ax2[i][1] = pack2(r8[kb],     r8[kb + 1]);
            ax2[i][2] = pack2(r0[kb + 8], r0[kb + 9]);
            ax2[i][3] = pack2(r8[kb + 8], r8[kb + 9]);
        }
#pragma unroll
        for (int jq = 0; jq < 2; jq++) {
            int kb = kg * 32 + jq * 16 + 2 * c;
            const float* r0 = g_ab + (size_t)srow * AD;
            const float* r8 = g_ab + (size_t)(srow + 8) * AD;
            auAB[jq][0] = pack2(r0[kb],     r0[kb + 1]);
            auAB[jq][1] = pack2(r8[kb],     r8[kb + 1]);
            auAB[jq][2] = pack2(r0[kb + 8], r0[kb + 9]);
            auAB[jq][3] = pack2(r8[kb + 8], r8[kb + 9]);
        }
    }

    // ---- preloop staging: round 0 x + u into side 0 ----
    if (tid == 0) {
        mbar_expect(mbarA, 32768);
        mbar_expect(mbarB, 32768);
        mbar_expect(mbarUb, 16384);
        asm volatile("fence.proxy.async;" ::: "memory");
        bulk_mc(smb + rank * 16384u,
                g_xbuf[0] + (size_t)mt * XWORDS + (size_t)rank * 4096,
                16384, ((rank & 1) == 0) ? mbarA : mbarB, 0xF);
        if (rank == 3)
            bulk_mc(smb + UO * 4u, g_ubuf + (size_t)mt * 4096, 16384, mbarUb, 0xF);
    }

    // ---- main loop: 256 rounds, gemm1 deferred into the DMA shadow ----
    for (int r = 0; r < NR; r++) {
        const int side = r & 1;
        const uint32_t xb = (uint32_t)(side * XWORDS);
        const uint32_t ub = (uint32_t)(UO + side * 4096);

        // 1. gemm2 (critical): A2 x + AB u_t + B u_{t+1}
        float d[4][4];
#pragma unroll
        for (int nn = 0; nn < 4; nn++)
#pragma unroll
            for (int e = 0; e < 4; e++) d[nn][e] = 0.0f;

        mbar_wait((kg >= 2) ? mbarB : mbarA, (uint32_t)(r & 1));
        {
            const uint32_t* xs = sm + xb + kg * 2048 + g * 4 + c;
#pragma unroll
            for (int i = 0; i < 16; i++) {
#pragma unroll
                for (int nn = 0; nn < 4; nn++) {
                    uint32_t b0 = xs[i * 128 + nn * 32];
                    uint32_t b1 = xs[i * 128 + nn * 32 + XHI];
                    mma_f16(d[nn], ax2[i][0], ax2[i][1], ax2[i][2], ax2[i][3], b0, b1);
                }
            }
        }
        mbar_wait(mbarUb + (r & 1) * 8, (uint32_t)((r >> 1) & 1));
        {
            const uint32_t* us = sm + ub + kg * 2 * 128 + g * 4 + c;
#pragma unroll
            for (int jq = 0; jq < 2; jq++) {
#pragma unroll
                for (int nn = 0; nn < 4; nn++) {
                    uint32_t b0 = us[jq * 128 + nn * 32];
                    uint32_t b1 = us[jq * 128 + nn * 32 + UHI];
                    mma_f16(d[nn], auAB[jq][0], auAB[jq][1], auAB[jq][2], auAB[jq][3], b0, b1);
                    uint32_t c0 = us[2048 + jq * 128 + nn * 32];
                    uint32_t c1 = us[2048 + jq * 128 + nn * 32 + UHI];
                    mma_f16(d[nn], auB[jq][0], auB[jq][1], auB[jq][2], auB[jq][3], c0, c1);
                }
            }
        }

        // 2. gemm2 partials -> slab2
        {
            int rb = w * GMS + g * RS + 2 * c;
#pragma unroll
            for (int nn = 0; nn < 4; nn++) {
                *(float2*)(red2 + rb + nn * 8) = make_float2(d[nn][0], d[nn][1]);
                *(float2*)(red2 + rb + 8 * RS + nn * 8) = make_float2(d[nn][2], d[nn][3]);
            }
        }
        __syncthreads();   // also absorbs warp0's late gemm1 partials of r-1

        // 3. reduce1 (round r-1, deferred) then reduce2 (this round)
        {
            int b = tid >> 3;
            int s4 = (tid & 7) * 4;
            int ssr = s4 >> 4;
            if (r > 0) {
                float a1[4] = {0.f, 0.f, 0.f, 0.f};
#pragma unroll
                for (int kk = 0; kk < 4; kk++) {
                    int wb = (kk * 2 + ssr) * GMS + b;
#pragma unroll
                    for (int i = 0; i < 4; i++)
                        a1[i] += red1[wb + ((s4 + i) & 15) * RS];
                }
                float* op1 = out + ((size_t)(m0 + b) * OUT_T + (2 * r - 1)) * SDIM + n0 + s4;
                *(float4*)op1 = make_float4(a1[0], a1[1], a1[2], a1[3]);
            }
            float a2v[4] = {0.f, 0.f, 0.f, 0.f};
#pragma unroll
            for (int kk = 0; kk < 4; kk++) {
                int wb = (kk * 2 + ssr) * GMS + b;
#pragma unroll
                for (int i = 0; i < 4; i++)
                    a2v[i] += red2[wb + ((s4 + i) & 15) * RS];
            }
            float* op2 = out + ((size_t)(m0 + b) * OUT_T + (2 * r + 2)) * SDIM + n0 + s4;
            *(float4*)op2 = make_float4(a2v[0], a2v[1], a2v[2], a2v[3]);

            int k2 = (n0 + s4) >> 1;
            int o16 = k2 >> 3, c2 = k2 & 7;
            size_t idx = (size_t)mt * XWORDS + (size_t)o16 * 128 + (size_t)b * 4
                       + (c2 & 3) + ((c2 & 4) ? XHI : 0);
            uint32_t* xp = g_xbuf[(r + 1) & 1] + idx;
            uint32_t w0 = pack2(a2v[0], a2v[1]);
            uint32_t w1 = pack2(a2v[2], a2v[3]);
            asm volatile("st.global.cg.v2.b32 [%0], {%1,%2};"
                         :: "l"(xp), "r"(w0), "r"(w1) : "memory");
        }

        // 4. publish x_{2r+2}
        __threadfence();
        __syncthreads();
        if (tid == 0)
            *((volatile unsigned*)&g_flag[mt][nt][0]) = base + 3 + r;

        // 5. warp0: poll + stage round r+1 (others go straight to gemm1)
        if (r + 1 < NR && tid < 32) {
            unsigned want = base + 3 + r;
            while ((int)(*((volatile unsigned*)&g_flag[mt][tid][0]) - want) < 0) { }
            if (tid == 0) {
                asm volatile("fence.proxy.async;" ::: "memory");
                mbar_expect(mbarA, 32768);
                mbar_expect(mbarB, 32768);
                mbar_expect(mbarUb + ((r + 1) & 1) * 8, 16384);
                bulk_mc(smb + (((r + 1) & 1) * XWORDS + rank * 4096u) * 4u,
                        g_xbuf[(r + 1) & 1] + (size_t)mt * XWORDS + (size_t)rank * 4096,
                        16384, ((rank & 1) == 0) ? mbarA : mbarB, 0xF);
                if (rank == 3)
                    bulk_mc(smb + (UO + ((r + 1) & 1) * 4096u) * 4u,
                            g_ubuf + ((size_t)(r + 1) * 4 + mt) * 4096,
                            16384, mbarUb + ((r + 1) & 1) * 8, 0xF);
            }
        }

        // 6. gemm1 (deferred output): A x + B u_t   (in the DMA shadow)
#pragma unroll
        for (int nn = 0; nn < 4; nn++)
#pragma unroll
            for (int e = 0; e < 4; e++) d[nn][e] = 0.0f;
        {
            const uint32_t* xs = sm + xb + kg * 2048 + g * 4 + c;
#pragma unroll
            for (int i = 0; i < 16; i++) {
#pragma unroll
                for (int nn = 0; nn < 4; nn++) {
                    uint32_t b0 = xs[i * 128 + nn * 32];
                    uint32_t b1 = xs[i * 128 + nn * 32 + XHI];
                    mma_f16(d[nn], axA[i][0], axA[i][1], axA[i][2], axA[i][3], b0, b1);
                }
            }
            const uint32_t* us = sm + ub + kg * 2 * 128 + g * 4 + c;
#pragma unroll
            for (int jq = 0; jq < 2; jq++) {
#pragma unroll
                for (int nn = 0; nn < 4; nn++) {
                    uint32_t b0 = us[jq * 128 + nn * 32];
                    uint32_t b1 = us[jq * 128 + nn * 32 + UHI];
                    mma_f16(d[nn], auB[jq][0], auB[jq][1], auB[jq][2], auB[jq][3], b0, b1);
                }
            }
        }
        // 7. gemm1 partials -> slab1 (reduced next round; NO sync here)
        {
            int rb = w * GMS + g * RS + 2 * c;
#pragma unroll
            for (int nn = 0; nn < 4; nn++) {
                *(float2*)(red1 + rb + nn * 8) = make_float2(d[nn][0], d[nn][1]);
                *(float2*)(red1 + rb + 8 * RS + nn * 8) = make_float2(d[nn][2], d[nn][3]);
            }
        }
    }

    // ---- drain: reduce1 of the last round ----
    __syncthreads();
    {
        int b = tid >> 3;
        int s4 = (tid & 7) * 4;
        int ssr = s4 >> 4;
        float a1[4] = {0.f, 0.f, 0.f, 0.f};
#pragma unroll
        for (int kk = 0; kk < 4; kk++) {
            int wb = (kk * 2 + ssr) * GMS + b;
#pragma unroll
            for (int i = 0; i < 4; i++)
                a1[i] += red1[wb + ((s4 + i) & 15) * RS];
        }
        float* op1 = out + ((size_t)(m0 + b) * OUT_T + (HH - 1)) * SDIM + n0 + s4;
        *(float4*)op1 = make_float4(a1[0], a1[1], a1[2], a1[3]);
    }

    if (bid == 0 && tid == 0) {
        __threadfence();
        *((volatile unsigned*)&g_release) = base + 3 + NR;
    }
}

extern "C" void kernel_launch(void* const* d_in, const int* in_sizes, int n_in,
                              void* d_out, int out_size)
{
    const float* x0 = (const float*)d_in[0];
    const float* u  = (const float*)d_in[1];
    const float* A  = (const float*)d_in[2];
    const float* Bm = (const float*)d_in[3];
    float* out = (float*)d_out;

    cudaFuncSetAttribute(ssm_v12_kernel,
                         cudaFuncAttributeMaxDynamicSharedMemorySize, SMEM_BYTES);

    ssm_v12_kernel<<<NCTA, NTHREADS, SMEM_BYTES>>>(x0, u, A, Bm, out);
}